// round 2
// baseline (speedup 1.0000x reference)
#include <cuda_runtime.h>

// ---------------- problem constants (fixed for this problem) ----------------
#define BB    2
#define SS    16
#define NN    5000
#define HH    64
#define EE    20000
#define NHEAD 4
#define HD    16
#define BSS   (BB*SS)      // 32
#define BNN   (BB*NN)      // 10000
#define NROWS (BSS*NN)     // 160000

// ---------------- scratch (device globals: allocation-free) ----------------
__device__ __align__(16) float g_x1[NROWS*HH];        // post-attention (B,S,N,H)
__device__ __align__(16) float g_x2[NROWS*HH];        // post-spatial
__device__ __align__(16) float g_P [NROWS*128];       // xs @ (Wa - Wb)
__device__ __align__(16) float g_Q [NROWS*128];       // xs @ Wb
__device__ __align__(16) float g_R [EE*128];          // edge_emb @ Wc + m_b1
__device__ __align__(16) float g_G [NROWS*128];       // scatter-add of gelu(h)
__device__ int   g_deg[NN];

__device__ __forceinline__ float gelu_f(float v) {
    return 0.5f * v * (1.0f + erff(v * 0.70710678118654752f));
}

// ---------------- K0: zero scratch that is accumulated into ----------------
__global__ void zero_kernel() {
    int idx = blockIdx.x * blockDim.x + threadIdx.x;   // grid 20000 x 256 = 5.12M
    float4 z = make_float4(0.f, 0.f, 0.f, 0.f);
    ((float4*)g_G)[idx] = z;                           // NROWS*128/4 = 5,120,000 exactly
    if (idx < NN) g_deg[idx] = 0;
}

// ---------------- K1: temporal attention + residual + LN -------------------
// one CTA (256 thr) handles 8 (b,n) sequences of length S=16
__global__ void attn_kernel(const float* __restrict__ x,
                            const float* __restrict__ Wi, const float* __restrict__ bi,
                            const float* __restrict__ Wo, const float* __restrict__ bo,
                            const float* __restrict__ tg, const float* __restrict__ tb)
{
    extern __shared__ float sm[];
    float* sWi  = sm;              // 64*192
    float* sWo  = sWi + 12288;     // 64*64
    float* sbi  = sWo + 4096;      // 192
    float* sbo  = sbi + 192;       // 64
    float* stg  = sbo + 64;        // 64
    float* stb  = stg + 64;        // 64
    float* sxt  = stb + 64;        // 16*64
    float* sqkv = sxt + 1024;      // 16*192
    float* sao  = sqkv + 3072;     // 16*64
    float* sy   = sao + 1024;      // 16*64
    float* smean= sy + 1024;       // 16
    float* sinv = smean + 16;      // 16

    int t = threadIdx.x;
    for (int i = t; i < 12288; i += 256) sWi[i] = Wi[i];
    for (int i = t; i < 4096;  i += 256) sWo[i] = Wo[i];
    if (t < 192) sbi[t] = bi[t];
    if (t < 64) { sbo[t] = bo[t]; stg[t] = tg[t]; stb[t] = tb[t]; }
    __syncthreads();

    for (int u = 0; u < 8; u++) {
        int bn = blockIdx.x * 8 + u;
        if (bn >= BNN) break;
        int b = bn / NN, n = bn % NN;

        // load xt[s][c] = x[b,s,n,c] (strided over s)
        for (int i = t; i < 1024; i += 256) {
            int s = i >> 6, c = i & 63;
            sxt[i] = x[((b*SS + s)*NN + n)*HH + c];
        }
        __syncthreads();

        // qkv = xt @ Wi + bi : col-per-thread, 16 rows in regs
        if (t < 192) {
            float acc[16];
            #pragma unroll
            for (int r = 0; r < 16; r++) acc[r] = sbi[t];
            for (int i = 0; i < 64; i++) {
                float w = sWi[i*192 + t];
                #pragma unroll
                for (int r = 0; r < 16; r++) acc[r] += sxt[r*64 + i] * w;
            }
            #pragma unroll
            for (int r = 0; r < 16; r++) sqkv[r*192 + t] = acc[r];
        }
        __syncthreads();

        // attention: thread = (head, query)
        if (t < 64) {
            int h = t >> 4, q = t & 15;
            float sc[16], mx = -1e30f;
            #pragma unroll
            for (int k = 0; k < 16; k++) {
                float a = 0.f;
                #pragma unroll
                for (int d = 0; d < 16; d++)
                    a += sqkv[q*192 + h*16 + d] * sqkv[k*192 + 64 + h*16 + d];
                a *= 0.25f;                 // 1/sqrt(hd)
                sc[k] = a; mx = fmaxf(mx, a);
            }
            float den = 0.f;
            #pragma unroll
            for (int k = 0; k < 16; k++) { sc[k] = expf(sc[k] - mx); den += sc[k]; }
            float inv = 1.f / den;
            #pragma unroll
            for (int d = 0; d < 16; d++) {
                float o = 0.f;
                #pragma unroll
                for (int k = 0; k < 16; k++) o += sc[k] * sqkv[k*192 + 128 + h*16 + d];
                sao[q*64 + h*16 + d] = o * inv;
            }
        }
        __syncthreads();

        // out projection + residual
        for (int i = t; i < 1024; i += 256) {
            int r = i >> 6, c = i & 63;
            float acc = sbo[c];
            #pragma unroll 8
            for (int k = 0; k < 64; k++) acc += sao[r*64 + k] * sWo[k*64 + c];
            sy[i] = sxt[i] + acc;
        }
        __syncthreads();

        // LayerNorm stats: 16 lanes per row
        {
            int r = t >> 4, l = t & 15;
            float4 v = *(const float4*)&sy[r*64 + l*4];
            float s  = v.x + v.y + v.z + v.w;
            float ss = v.x*v.x + v.y*v.y + v.z*v.z + v.w*v.w;
            #pragma unroll
            for (int o = 1; o < 16; o <<= 1) {
                s  += __shfl_xor_sync(0xffffffffu, s,  o, 16);
                ss += __shfl_xor_sync(0xffffffffu, ss, o, 16);
            }
            if (l == 0) {
                float m = s * (1.f/64.f);
                float var = ss * (1.f/64.f) - m*m;
                smean[r] = m; sinv[r] = rsqrtf(var + 1e-5f);
            }
        }
        __syncthreads();

        for (int i = t; i < 1024; i += 256) {
            int r = i >> 6, c = i & 63;
            g_x1[((b*SS + r)*NN + n)*HH + c] = (sy[i] - smean[r]) * sinv[r] * stg[c] + stb[c];
        }
        __syncthreads();
    }
}

// ---------------- K2: edge embedding -> R, and degrees ---------------------
__global__ void edge_emb_kernel(const float* __restrict__ ea,
                                const int*   __restrict__ ei,
                                const float* __restrict__ ew1, const float* __restrict__ eb1,
                                const float* __restrict__ ew2, const float* __restrict__ eb2,
                                const float* __restrict__ mw1, const float* __restrict__ mb1)
{
    extern __shared__ float sm[];
    float* sEw2 = sm;            // 64*64
    float* sWc  = sEw2 + 4096;   // 64*128 (= m_w1 rows 128..191)
    float* sew1 = sWc + 8192;    // 64
    float* seb1 = sew1 + 64;     // 64
    float* seb2 = seb1 + 64;     // 64
    float* smb1 = seb2 + 64;     // 128
    float* semb = smb1 + 128;    // 64
    float* semb2= semb + 64;     // 64

    int t = threadIdx.x;   // 128
    for (int i = t; i < 4096; i += 128) sEw2[i] = ew2[i];
    for (int i = t; i < 8192; i += 128) sWc[i]  = mw1[128*128 + i];
    if (t < 64) { sew1[t] = ew1[t]; seb1[t] = eb1[t]; seb2[t] = eb2[t]; }
    smb1[t] = mb1[t];
    __syncthreads();

    for (int e = blockIdx.x; e < EE; e += gridDim.x) {
        if (t == 0) atomicAdd(&g_deg[ei[EE + e]], 1);
        if (t < 64) semb[t] = gelu_f(ea[e] * sew1[t] + seb1[t]);
        __syncthreads();
        if (t < 64) {
            float a = seb2[t];
            #pragma unroll 8
            for (int i = 0; i < 64; i++) a += semb[i] * sEw2[i*64 + t];
            semb2[t] = a;
        }
        __syncthreads();
        {
            float a = smb1[t];
            #pragma unroll 8
            for (int i = 0; i < 64; i++) a += semb2[i] * sWc[i*128 + t];
            g_R[e*128 + t] = a;
        }
        __syncthreads();
    }
}

// ---------------- K3: P,Q node GEMM (160000 x 64 @ 64 x 256) ----------------
__global__ void pq_kernel(const float* __restrict__ mw1)
{
    extern __shared__ float sm[];
    float* sW = sm;          // 64 x 256 : [ Wa-Wb | Wb ]
    float* sX = sm + 16384;  // 16 x 64
    int t = threadIdx.x;     // 256
    for (int idx = t; idx < 16384; idx += 256) {
        int i = idx >> 8, j = idx & 255;
        sW[idx] = (j < 128) ? (mw1[i*128 + j] - mw1[(64+i)*128 + j])
                            :  mw1[(64+i)*128 + (j-128)];
    }
    int rbase = blockIdx.x * 16;
    for (int i = t; i < 1024; i += 256)
        sX[i] = g_x1[(rbase + (i >> 6))*64 + (i & 63)];
    __syncthreads();

    int c = t;
    float acc[16];
    #pragma unroll
    for (int r = 0; r < 16; r++) acc[r] = 0.f;
    for (int i = 0; i < 64; i++) {
        float w = sW[i*256 + c];
        #pragma unroll
        for (int r = 0; r < 16; r++) acc[r] += sX[r*64 + i] * w;
    }
    float* dst = (c < 128) ? (g_P + rbase*128 + c) : (g_Q + rbase*128 + (c - 128));
    #pragma unroll
    for (int r = 0; r < 16; r++) dst[r*128] = acc[r];
}

// ---------------- K4: per-edge gelu + scatter-add into G --------------------
// warp per (edge, batch-slice); e-major so 32 consecutive warps share R/src/dst
__global__ void edge_aggr_kernel(const int* __restrict__ ei)
{
    int w = (blockIdx.x * blockDim.x + threadIdx.x) >> 5;  // 0 .. 640000
    if (w >= BSS*EE) return;
    int lane = threadIdx.x & 31;
    int e = w >> 5;          // edge
    int b = w & 31;          // batch-slice
    int src = ei[e], dst = ei[EE + e];
    const float4* P4 = (const float4*)(g_P + (b*NN + src)*128);
    const float4* Q4 = (const float4*)(g_Q + (b*NN + dst)*128);
    const float4* R4 = (const float4*)(g_R + e*128);
    float4 p = P4[lane], q = Q4[lane], r = R4[lane];
    float hx = gelu_f(p.x + q.x + r.x);
    float hy = gelu_f(p.y + q.y + r.y);
    float hz = gelu_f(p.z + q.z + r.z);
    float hw = gelu_f(p.w + q.w + r.w);
    float* G = g_G + (b*NN + dst)*128 + lane*4;
    atomicAdd(G + 0, hx); atomicAdd(G + 1, hy);
    atomicAdd(G + 2, hz); atomicAdd(G + 3, hw);
}

// ---------------- K5: aggr GEMM + update MLP + residual + LN ----------------
__global__ void update_kernel(const float* __restrict__ mw2, const float* __restrict__ mb2,
                              const float* __restrict__ uw1, const float* __restrict__ ub1,
                              const float* __restrict__ uw2, const float* __restrict__ ub2,
                              const float* __restrict__ sg,  const float* __restrict__ sb)
{
    extern __shared__ float sm[];
    float* sW2  = sm;             // 128x64
    float* sU1  = sW2 + 8192;     // 128x64
    float* sU2  = sU1 + 8192;     // 64x64
    float* smb2 = sU2 + 4096;     // 64
    float* sub1 = smb2 + 64;
    float* sub2 = sub1 + 64;
    float* ssg  = sub2 + 64;
    float* ssb  = ssg + 64;
    float* sG   = ssb + 64;       // 16x128
    float* sUin = sG + 2048;      // 16x128
    float* sXs  = sUin + 2048;    // 16x64
    float* sHid = sXs + 1024;     // 16x64
    float* sY   = sHid + 1024;    // 16x64
    float* smean= sY + 1024;      // 16
    float* sinv = smean + 16;     // 16
    float* sdeg = sinv + 16;      // 16

    int t = threadIdx.x;  // 256
    for (int i = t; i < 8192; i += 256) { sW2[i] = mw2[i]; sU1[i] = uw1[i]; }
    for (int i = t; i < 4096; i += 256) sU2[i] = uw2[i];
    if (t < 64) { smb2[t] = mb2[t]; sub1[t] = ub1[t]; sub2[t] = ub2[t]; ssg[t] = sg[t]; ssb[t] = sb[t]; }

    int rbase = blockIdx.x * 16;
    for (int i = t; i < 2048; i += 256) sG[i] = g_G[(rbase + (i >> 7))*128 + (i & 127)];
    for (int i = t; i < 1024; i += 256) {
        float v = g_x1[(rbase + (i >> 6))*64 + (i & 63)];
        sXs[i] = v;
        sUin[(i >> 6)*128 + (i & 63)] = v;
    }
    if (t < 16) sdeg[t] = (float)g_deg[(rbase + t) % NN];
    __syncthreads();

    int c = t & 63, rg = t >> 6;

    // aggr = G @ m_w2 + deg * m_b2  -> sUin[r][64+c]
    #pragma unroll
    for (int k = 0; k < 4; k++) {
        int r = rg + 4*k;
        float acc = sdeg[r] * smb2[c];
        #pragma unroll 8
        for (int i = 0; i < 128; i++) acc += sG[r*128 + i] * sW2[i*64 + c];
        sUin[r*128 + 64 + c] = acc;
    }
    __syncthreads();

    // hid = gelu(u_in @ u_w1 + u_b1)
    #pragma unroll
    for (int k = 0; k < 4; k++) {
        int r = rg + 4*k;
        float acc = sub1[c];
        #pragma unroll 8
        for (int i = 0; i < 128; i++) acc += sUin[r*128 + i] * sU1[i*64 + c];
        sHid[r*64 + c] = gelu_f(acc);
    }
    __syncthreads();

    // so = hid @ u_w2 + u_b2 ; y = xs + so
    #pragma unroll
    for (int k = 0; k < 4; k++) {
        int r = rg + 4*k;
        float acc = sub2[c];
        #pragma unroll 8
        for (int i = 0; i < 64; i++) acc += sHid[r*64 + i] * sU2[i*64 + c];
        sY[r*64 + c] = sXs[r*64 + c] + acc;
    }
    __syncthreads();

    // LN
    {
        int r = t >> 4, l = t & 15;
        float4 v = *(const float4*)&sY[r*64 + l*4];
        float s  = v.x + v.y + v.z + v.w;
        float ss = v.x*v.x + v.y*v.y + v.z*v.z + v.w*v.w;
        #pragma unroll
        for (int o = 1; o < 16; o <<= 1) {
            s  += __shfl_xor_sync(0xffffffffu, s,  o, 16);
            ss += __shfl_xor_sync(0xffffffffu, ss, o, 16);
        }
        if (l == 0) {
            float m = s * (1.f/64.f);
            float var = ss * (1.f/64.f) - m*m;
            smean[r] = m; sinv[r] = rsqrtf(var + 1e-5f);
        }
    }
    __syncthreads();
    for (int i = t; i < 1024; i += 256) {
        int r = i >> 6, cc = i & 63;
        g_x2[(rbase + r)*64 + cc] = (sY[i] - smean[r]) * sinv[r] * ssg[cc] + ssb[cc];
    }
}

// ---------------- K6: FFN + residual + LN -> d_out --------------------------
__global__ void ffn_kernel(const float* __restrict__ fw1, const float* __restrict__ fb1,
                           const float* __restrict__ fw2, const float* __restrict__ fb2,
                           const float* __restrict__ fg,  const float* __restrict__ fb,
                           float* __restrict__ out)
{
    extern __shared__ float sm[];
    float* sW1 = sm;            // 64x256
    float* sW2 = sW1 + 16384;   // 256x64
    float* sb1 = sW2 + 16384;   // 256
    float* sb2 = sb1 + 256;     // 64
    float* sfg = sb2 + 64;
    float* sfb = sfg + 64;
    float* sX  = sfb + 64;      // 16x64
    float* sH  = sX + 1024;     // 16x256
    float* sY  = sH + 4096;     // 16x64
    float* smean = sY + 1024;   // 16
    float* sinv  = smean + 16;  // 16

    int t = threadIdx.x;  // 256
    for (int i = t; i < 16384; i += 256) { sW1[i] = fw1[i]; sW2[i] = fw2[i]; }
    sb1[t] = fb1[t];
    if (t < 64) { sb2[t] = fb2[t]; sfg[t] = fg[t]; sfb[t] = fb[t]; }

    int rbase = blockIdx.x * 16;
    for (int i = t; i < 1024; i += 256) sX[i] = g_x2[(rbase + (i >> 6))*64 + (i & 63)];
    __syncthreads();

    // H = gelu(X @ W1 + b1) : col-per-thread, 16 rows in regs
    {
        int c = t;
        float acc[16];
        #pragma unroll
        for (int r = 0; r < 16; r++) acc[r] = sb1[c];
        for (int i = 0; i < 64; i++) {
            float w = sW1[i*256 + c];
            #pragma unroll
            for (int r = 0; r < 16; r++) acc[r] += sX[r*64 + i] * w;
        }
        #pragma unroll
        for (int r = 0; r < 16; r++) sH[r*256 + c] = gelu_f(acc[r]);
    }
    __syncthreads();

    // Y = X + H @ W2 + b2
    {
        int c = t & 63, rg = t >> 6;
        #pragma unroll
        for (int k = 0; k < 4; k++) {
            int r = rg + 4*k;
            float acc = sb2[c];
            #pragma unroll 8
            for (int i = 0; i < 256; i++) acc += sH[r*256 + i] * sW2[i*64 + c];
            sY[r*64 + c] = sX[r*64 + c] + acc;
        }
    }
    __syncthreads();

    // LN
    {
        int r = t >> 4, l = t & 15;
        float4 v = *(const float4*)&sY[r*64 + l*4];
        float s  = v.x + v.y + v.z + v.w;
        float ss = v.x*v.x + v.y*v.y + v.z*v.z + v.w*v.w;
        #pragma unroll
        for (int o = 1; o < 16; o <<= 1) {
            s  += __shfl_xor_sync(0xffffffffu, s,  o, 16);
            ss += __shfl_xor_sync(0xffffffffu, ss, o, 16);
        }
        if (l == 0) {
            float m = s * (1.f/64.f);
            float var = ss * (1.f/64.f) - m*m;
            smean[r] = m; sinv[r] = rsqrtf(var + 1e-5f);
        }
    }
    __syncthreads();
    for (int i = t; i < 1024; i += 256) {
        int r = i >> 6, cc = i & 63;
        out[(rbase + r)*64 + cc] = (sY[i] - smean[r]) * sinv[r] * sfg[cc] + sfb[cc];
    }
}

// ---------------- host launcher ---------------------------------------------
extern "C" void kernel_launch(void* const* d_in, const int* in_sizes, int n_in,
                              void* d_out, int out_size)
{
    (void)in_sizes; (void)n_in; (void)out_size;
    const float* x    = (const float*)d_in[0];
    const int*   ei   = (const int*)  d_in[1];
    const float* ea   = (const float*)d_in[2];
    const float* ipw  = (const float*)d_in[3];
    const float* ipb  = (const float*)d_in[4];
    const float* opw  = (const float*)d_in[5];
    const float* opb  = (const float*)d_in[6];
    const float* tng  = (const float*)d_in[7];
    const float* tnb  = (const float*)d_in[8];
    const float* ew1  = (const float*)d_in[9];
    const float* eb1  = (const float*)d_in[10];
    const float* ew2  = (const float*)d_in[11];
    const float* eb2  = (const float*)d_in[12];
    const float* mw1  = (const float*)d_in[13];
    const float* mb1  = (const float*)d_in[14];
    const float* mw2  = (const float*)d_in[15];
    const float* mb2  = (const float*)d_in[16];
    const float* uw1  = (const float*)d_in[17];
    const float* ub1  = (const float*)d_in[18];
    const float* uw2  = (const float*)d_in[19];
    const float* ub2  = (const float*)d_in[20];
    const float* sng  = (const float*)d_in[21];
    const float* snb  = (const float*)d_in[22];
    const float* fw1  = (const float*)d_in[23];
    const float* fb1  = (const float*)d_in[24];
    const float* fw2  = (const float*)d_in[25];
    const float* fb2  = (const float*)d_in[26];
    const float* fng  = (const float*)d_in[27];
    const float* fnb  = (const float*)d_in[28];
    float* out = (float*)d_out;

    const int SM_K1 = 22944 * 4;   // 91776 B
    const int SM_K2 = 12736 * 4;   // 50944 B
    const int SM_K3 = 17408 * 4;   // 69632 B
    const int SM_K5 = 28016 * 4;   // 112064 B
    const int SM_K6 = 39392 * 4;   // 157568 B
    cudaFuncSetAttribute(attn_kernel,     cudaFuncAttributeMaxDynamicSharedMemorySize, SM_K1);
    cudaFuncSetAttribute(edge_emb_kernel, cudaFuncAttributeMaxDynamicSharedMemorySize, SM_K2);
    cudaFuncSetAttribute(pq_kernel,       cudaFuncAttributeMaxDynamicSharedMemorySize, SM_K3);
    cudaFuncSetAttribute(update_kernel,   cudaFuncAttributeMaxDynamicSharedMemorySize, SM_K5);
    cudaFuncSetAttribute(ffn_kernel,      cudaFuncAttributeMaxDynamicSharedMemorySize, SM_K6);

    zero_kernel      <<<20000, 256>>>();
    attn_kernel      <<<1250, 256, SM_K1>>>(x, ipw, ipb, opw, opb, tng, tnb);
    edge_emb_kernel  <<<256, 128, SM_K2>>>(ea, ei, ew1, eb1, ew2, eb2, mw1, mb1);
    pq_kernel        <<<10000, 256, SM_K3>>>(mw1);
    edge_aggr_kernel <<<80000, 256>>>(ei);
    update_kernel    <<<10000, 256, SM_K5>>>(mw2, mb2, uw1, ub1, uw2, ub2, sng, snb);
    ffn_kernel       <<<10000, 256, SM_K6>>>(fw1, fb1, fw2, fb2, fng, fnb, out);
}

// round 3
// speedup vs baseline: 1.4171x; 1.4171x over previous
#include <cuda_runtime.h>

// ---------------- problem constants ----------------
#define BB    2
#define SS    16
#define NN    5000
#define HH    64
#define EE    20000
#define BSS   (BB*SS)      // 32
#define BNN   (BB*NN)      // 10000
#define NROWS (BSS*NN)     // 160000

// ---------------- scratch (device globals) ----------------
__device__ __align__(16) float g_x1[NROWS*HH];
__device__ __align__(16) float g_x2[NROWS*HH];
__device__ __align__(16) float g_P [NROWS*128];
__device__ __align__(16) float g_Q [NROWS*128];
__device__ __align__(16) float g_R [EE*128];
__device__ __align__(16) float g_G [NROWS*128];
__device__ int  g_cnt[NN];
__device__ int  g_cur[NN];
__device__ int  g_off[NN+1];
__device__ int2 g_epk[EE];     // (src, e) sorted by dst

__device__ __forceinline__ float gelu_f(float v) {
    return 0.5f * v * (1.0f + erff(v * 0.70710678118654752f));
}

// ---------------- CSR build ----------------
__global__ void csr_zero_kernel() {
    int i = blockIdx.x * blockDim.x + threadIdx.x;
    if (i < NN) g_cnt[i] = 0;
}
__global__ void csr_count_kernel(const int* __restrict__ ei) {
    int e = blockIdx.x * blockDim.x + threadIdx.x;
    if (e < EE) atomicAdd(&g_cnt[ei[EE + e]], 1);
}
__global__ void csr_scan_kernel() {
    __shared__ int sbuf[1024];
    __shared__ int scarry;
    int t = threadIdx.x;
    if (t == 0) scarry = 0;
    __syncthreads();
    for (int ch = 0; ch < 5; ch++) {
        int idx = ch * 1024 + t;
        int v = (idx < NN) ? g_cnt[idx] : 0;
        sbuf[t] = v; __syncthreads();
        for (int o = 1; o < 1024; o <<= 1) {
            int x = (t >= o) ? sbuf[t - o] : 0;
            __syncthreads();
            sbuf[t] += x;
            __syncthreads();
        }
        int incl = sbuf[t];
        int base = scarry;
        if (idx < NN) { int off = base + incl - v; g_off[idx] = off; g_cur[idx] = off; }
        __syncthreads();
        if (t == 1023) scarry = base + sbuf[1023];
        __syncthreads();
    }
    if (t == 0) g_off[NN] = scarry;
}
__global__ void csr_fill_kernel(const int* __restrict__ ei) {
    int e = blockIdx.x * blockDim.x + threadIdx.x;
    if (e < EE) {
        int dst = ei[EE + e];
        int pos = atomicAdd(&g_cur[dst], 1);
        g_epk[pos] = make_int2(ei[e], e);
    }
}

// ---------------- K1: temporal attention + residual + LN -------------------
// 256 threads, 8 (b,n) sequences per block; transposed smem layouts (pad 20)
__global__ __launch_bounds__(256, 2) void attn_kernel(
    const float* __restrict__ x,
    const float* __restrict__ Wi, const float* __restrict__ bi,
    const float* __restrict__ Wo, const float* __restrict__ bo,
    const float* __restrict__ tg, const float* __restrict__ tb)
{
    extern __shared__ float sm[];
    float* sWi   = sm;              // 64*192
    float* sWo   = sWi + 12288;     // 64*64
    float* sbi   = sWo + 4096;      // 192
    float* sbo   = sbi + 192;       // 64
    float* stg   = sbo + 64;        // 64
    float* stb   = stg + 64;        // 64
    float* sxtT  = stb + 64;        // 64*20 [c][s]
    float* sqkvT = sxtT + 1280;     // 192*20 [j][s]
    float* saoT  = sqkvT + 3840;    // 64*20 [d][s]
    float* sy    = saoT + 1280;     // 16*64
    float* smean = sy + 1024;       // 16
    float* sinv  = smean + 16;      // 16

    int t = threadIdx.x;
    for (int i = t; i < 12288; i += 256) sWi[i] = Wi[i];
    for (int i = t; i < 4096;  i += 256) sWo[i] = Wo[i];
    if (t < 192) sbi[t] = bi[t];
    if (t < 64) { sbo[t] = bo[t]; stg[t] = tg[t]; stb[t] = tb[t]; }
    __syncthreads();

    for (int u = 0; u < 8; u++) {
        int bn = blockIdx.x * 8 + u;
        int b = bn / NN, n = bn % NN;

        // load transposed: sxtT[c*20+s] = x[b,s,n,c]
        for (int i = t; i < 1024; i += 256) {
            int c = i & 63, s = i >> 6;
            sxtT[c*20 + s] = x[((b*SS + s)*NN + n)*HH + c];
        }
        __syncthreads();

        // qkv: col-per-thread (192 cols), 16 rows in regs
        if (t < 192) {
            int j = t;
            float acc[16];
            #pragma unroll
            for (int r = 0; r < 16; r++) acc[r] = sbi[j];
            for (int i = 0; i < 64; i++) {
                float w = sWi[i*192 + j];
                const float4* xv = (const float4*)(sxtT + i*20);
                float4 a0 = xv[0], a1 = xv[1], a2 = xv[2], a3 = xv[3];
                acc[0]+=a0.x*w; acc[1]+=a0.y*w; acc[2]+=a0.z*w; acc[3]+=a0.w*w;
                acc[4]+=a1.x*w; acc[5]+=a1.y*w; acc[6]+=a1.z*w; acc[7]+=a1.w*w;
                acc[8]+=a2.x*w; acc[9]+=a2.y*w; acc[10]+=a2.z*w; acc[11]+=a2.w*w;
                acc[12]+=a3.x*w; acc[13]+=a3.y*w; acc[14]+=a3.z*w; acc[15]+=a3.w*w;
            }
            float4* qv = (float4*)(sqkvT + j*20);
            qv[0] = make_float4(acc[0],acc[1],acc[2],acc[3]);
            qv[1] = make_float4(acc[4],acc[5],acc[6],acc[7]);
            qv[2] = make_float4(acc[8],acc[9],acc[10],acc[11]);
            qv[3] = make_float4(acc[12],acc[13],acc[14],acc[15]);
        }
        __syncthreads();

        // attention: thread = (head, query)
        if (t < 64) {
            int h = t >> 4, q = t & 15;
            float sc[16];
            #pragma unroll
            for (int k = 0; k < 16; k++) sc[k] = 0.f;
            #pragma unroll
            for (int d = 0; d < 16; d++) {
                float qv = sqkvT[(h*16 + d)*20 + q];
                const float4* kk = (const float4*)(sqkvT + (64 + h*16 + d)*20);
                float4 k0 = kk[0], k1 = kk[1], k2 = kk[2], k3 = kk[3];
                sc[0]+=qv*k0.x; sc[1]+=qv*k0.y; sc[2]+=qv*k0.z; sc[3]+=qv*k0.w;
                sc[4]+=qv*k1.x; sc[5]+=qv*k1.y; sc[6]+=qv*k1.z; sc[7]+=qv*k1.w;
                sc[8]+=qv*k2.x; sc[9]+=qv*k2.y; sc[10]+=qv*k2.z; sc[11]+=qv*k2.w;
                sc[12]+=qv*k3.x; sc[13]+=qv*k3.y; sc[14]+=qv*k3.z; sc[15]+=qv*k3.w;
            }
            float mx = -1e30f;
            #pragma unroll
            for (int k = 0; k < 16; k++) { sc[k] *= 0.25f; mx = fmaxf(mx, sc[k]); }
            float den = 0.f;
            #pragma unroll
            for (int k = 0; k < 16; k++) { sc[k] = expf(sc[k] - mx); den += sc[k]; }
            float inv = 1.f / den;
            #pragma unroll
            for (int d = 0; d < 16; d++) {
                const float4* vv = (const float4*)(sqkvT + (128 + h*16 + d)*20);
                float4 v0 = vv[0], v1 = vv[1], v2 = vv[2], v3 = vv[3];
                float o = sc[0]*v0.x + sc[1]*v0.y + sc[2]*v0.z + sc[3]*v0.w
                        + sc[4]*v1.x + sc[5]*v1.y + sc[6]*v1.z + sc[7]*v1.w
                        + sc[8]*v2.x + sc[9]*v2.y + sc[10]*v2.z + sc[11]*v2.w
                        + sc[12]*v3.x + sc[13]*v3.y + sc[14]*v3.z + sc[15]*v3.w;
                saoT[(h*16 + d)*20 + q] = o * inv;
            }
        }
        __syncthreads();

        // out projection + residual: (c, rg) 64x4, 4 rows each
        {
            int c = t & 63, rg = t >> 6;
            float a0 = sbo[c], a1 = a0, a2 = a0, a3 = a0;
            for (int i = 0; i < 64; i++) {
                float4 f = *(const float4*)(saoT + i*20 + rg*4);
                float w = sWo[i*64 + c];
                a0 += f.x*w; a1 += f.y*w; a2 += f.z*w; a3 += f.w*w;
            }
            int r = rg * 4;
            sy[(r+0)*64 + c] = sxtT[c*20 + r+0] + a0;
            sy[(r+1)*64 + c] = sxtT[c*20 + r+1] + a1;
            sy[(r+2)*64 + c] = sxtT[c*20 + r+2] + a2;
            sy[(r+3)*64 + c] = sxtT[c*20 + r+3] + a3;
        }
        __syncthreads();

        // LayerNorm
        {
            int r = t >> 4, l = t & 15;
            float4 v = *(const float4*)&sy[r*64 + l*4];
            float s  = v.x + v.y + v.z + v.w;
            float ss = v.x*v.x + v.y*v.y + v.z*v.z + v.w*v.w;
            #pragma unroll
            for (int o = 1; o < 16; o <<= 1) {
                s  += __shfl_xor_sync(0xffffffffu, s,  o, 16);
                ss += __shfl_xor_sync(0xffffffffu, ss, o, 16);
            }
            if (l == 0) {
                float m = s * (1.f/64.f);
                float var = ss * (1.f/64.f) - m*m;
                smean[r] = m; sinv[r] = rsqrtf(var + 1e-5f);
            }
        }
        __syncthreads();
        for (int i = t; i < 1024; i += 256) {
            int r = i >> 6, c = i & 63;
            g_x1[((b*SS + r)*NN + n)*HH + c] = (sy[i] - smean[r]) * sinv[r] * stg[c] + stb[c];
        }
        __syncthreads();
    }
}

// ---------------- K2: edge embedding -> R ---------------------
__global__ void edge_emb_kernel(const float* __restrict__ ea,
                                const float* __restrict__ ew1, const float* __restrict__ eb1,
                                const float* __restrict__ ew2, const float* __restrict__ eb2,
                                const float* __restrict__ mw1, const float* __restrict__ mb1)
{
    extern __shared__ float sm[];
    float* sEw2 = sm;            // 64*64
    float* sWc  = sEw2 + 4096;   // 64*128
    float* sew1 = sWc + 8192;
    float* seb1 = sew1 + 64;
    float* seb2 = seb1 + 64;
    float* smb1 = seb2 + 64;     // 128
    float* semb = smb1 + 128;    // 64
    float* semb2= semb + 64;     // 64

    int t = threadIdx.x;   // 128
    for (int i = t; i < 4096; i += 128) sEw2[i] = ew2[i];
    for (int i = t; i < 8192; i += 128) sWc[i]  = mw1[128*128 + i];
    if (t < 64) { sew1[t] = ew1[t]; seb1[t] = eb1[t]; seb2[t] = eb2[t]; }
    smb1[t] = mb1[t];
    __syncthreads();

    for (int e = blockIdx.x; e < EE; e += gridDim.x) {
        if (t < 64) semb[t] = gelu_f(ea[e] * sew1[t] + seb1[t]);
        __syncthreads();
        if (t < 64) {
            float a = seb2[t];
            #pragma unroll 8
            for (int i = 0; i < 64; i++) a += semb[i] * sEw2[i*64 + t];
            semb2[t] = a;
        }
        __syncthreads();
        {
            float a = smb1[t];
            #pragma unroll 8
            for (int i = 0; i < 64; i++) a += semb2[i] * sWc[i*128 + t];
            g_R[e*128 + t] = a;
        }
        __syncthreads();
    }
}

// ---------------- K3: P,Q node GEMM (32 rows/block, 512 thr) ----------------
__global__ __launch_bounds__(512, 1) void pq_kernel(const float* __restrict__ mw1)
{
    extern __shared__ float sm[];
    float* sW  = sm;           // 64 x 256 : [ Wa-Wb | Wb ]
    float* sXT = sm + 16384;   // [i<64][r<32] pad 36

    int t = threadIdx.x;       // 512
    for (int idx = t; idx < 16384; idx += 512) {
        int i = idx >> 8, j = idx & 255;
        sW[idx] = (j < 128) ? (mw1[i*128 + j] - mw1[(64+i)*128 + j])
                            :  mw1[(64+i)*128 + (j-128)];
    }
    int rbase = blockIdx.x * 32;
    for (int idx = t; idx < 2048; idx += 512) {
        int c = idx & 63, r = idx >> 6;
        sXT[c*36 + r] = g_x1[(rbase + r)*64 + c];
    }
    __syncthreads();

    int c = t & 255, half = t >> 8;
    float acc[16];
    #pragma unroll
    for (int r = 0; r < 16; r++) acc[r] = 0.f;
    for (int i = 0; i < 64; i++) {
        float w = sW[i*256 + c];
        const float4* xv = (const float4*)(sXT + i*36 + half*16);
        float4 a0 = xv[0], a1 = xv[1], a2 = xv[2], a3 = xv[3];
        acc[0]+=a0.x*w; acc[1]+=a0.y*w; acc[2]+=a0.z*w; acc[3]+=a0.w*w;
        acc[4]+=a1.x*w; acc[5]+=a1.y*w; acc[6]+=a1.z*w; acc[7]+=a1.w*w;
        acc[8]+=a2.x*w; acc[9]+=a2.y*w; acc[10]+=a2.z*w; acc[11]+=a2.w*w;
        acc[12]+=a3.x*w; acc[13]+=a3.y*w; acc[14]+=a3.z*w; acc[15]+=a3.w*w;
    }
    float* dp = (c < 128) ? (g_P + (rbase + half*16)*128 + c)
                          : (g_Q + (rbase + half*16)*128 + (c - 128));
    #pragma unroll
    for (int r = 0; r < 16; r++) dp[r*128] = acc[r];
}

// ---------------- K4: CSR gather aggregation (no atomics) -------------------
__global__ __launch_bounds__(256) void aggr_kernel()
{
    int w = (blockIdx.x * 256 + threadIdx.x) >> 5;   // 0..159999
    int lane = threadIdx.x & 31;
    int b = w & 31, dst = w >> 5;                     // b<32, dst<5000
    int row = b * NN + dst;
    float4 q = ((const float4*)g_Q)[row*32 + lane];
    float4 acc = make_float4(0.f, 0.f, 0.f, 0.f);
    int s = g_off[dst], e = g_off[dst+1];
    for (int k = s; k < e; k++) {
        int2 pe = g_epk[k];
        float4 p = ((const float4*)g_P)[(b*NN + pe.x)*32 + lane];
        float4 r = ((const float4*)g_R)[pe.y*32 + lane];
        acc.x += gelu_f(p.x + q.x + r.x);
        acc.y += gelu_f(p.y + q.y + r.y);
        acc.z += gelu_f(p.z + q.z + r.z);
        acc.w += gelu_f(p.w + q.w + r.w);
    }
    ((float4*)g_G)[row*32 + lane] = acc;
}

// ---------------- K5: aggr GEMM + update MLP + residual + LN ----------------
__global__ __launch_bounds__(512, 1) void update_kernel(
    const float* __restrict__ mw2, const float* __restrict__ mb2,
    const float* __restrict__ uw1, const float* __restrict__ ub1,
    const float* __restrict__ uw2, const float* __restrict__ ub2,
    const float* __restrict__ sg,  const float* __restrict__ sb)
{
    extern __shared__ float sm[];
    float* sW2m = sm;              // 128x64
    float* sU1  = sW2m + 8192;     // 128x64
    float* sU2  = sU1 + 8192;      // 64x64
    float* smb2 = sU2 + 4096;      // 64
    float* sub1 = smb2 + 64;
    float* sub2 = sub1 + 64;
    float* ssg  = sub2 + 64;
    float* ssb  = ssg + 64;
    float* sGT  = ssb + 64;        // [i<128][r<32] pad36 = 4608
    float* sUinT= sGT + 4608;      // [i<128][r<32] pad36 = 4608
    float* sHidT= sUinT + 4608;    // [i<64][r<32] pad36 = 2304
    float* sY   = sHidT + 2304;    // 32x64
    float* smean= sY + 2048;       // 32
    float* sinv = smean + 32;      // 32
    float* sdeg = sinv + 32;       // 32

    int t = threadIdx.x;  // 512
    for (int i = t; i < 8192; i += 512) { sW2m[i] = mw2[i]; sU1[i] = uw1[i]; }
    for (int i = t; i < 4096; i += 512) sU2[i] = uw2[i];
    if (t < 64) { smb2[t] = mb2[t]; sub1[t] = ub1[t]; sub2[t] = ub2[t]; ssg[t] = sg[t]; ssb[t] = sb[t]; }

    int rbase = blockIdx.x * 32;
    for (int idx = t; idx < 4096; idx += 512) {
        int c = idx & 127, r = idx >> 7;
        sGT[c*36 + r] = g_G[(rbase + r)*128 + c];
    }
    for (int idx = t; idx < 2048; idx += 512) {
        int c = idx & 63, r = idx >> 6;
        sUinT[c*36 + r] = g_x1[(rbase + r)*64 + c];
    }
    if (t < 32) {
        int n = (rbase + t) % NN;
        sdeg[t] = (float)(g_off[n+1] - g_off[n]);
    }
    __syncthreads();

    int c = t & 63, rg = t >> 6;   // 64 cols x 8 row-groups of 4

    // aggr = G @ m_w2 + deg * m_b2  -> sUinT rows 64..127
    {
        float wb = smb2[c];
        float a0 = sdeg[rg*4+0]*wb, a1 = sdeg[rg*4+1]*wb,
              a2 = sdeg[rg*4+2]*wb, a3 = sdeg[rg*4+3]*wb;
        for (int i = 0; i < 128; i++) {
            float4 f = *(const float4*)(sGT + i*36 + rg*4);
            float w = sW2m[i*64 + c];
            a0 += f.x*w; a1 += f.y*w; a2 += f.z*w; a3 += f.w*w;
        }
        *(float4*)(sUinT + (64+c)*36 + rg*4) = make_float4(a0, a1, a2, a3);
    }
    __syncthreads();

    // hid = gelu(u_in @ u_w1 + u_b1)
    {
        float a0 = sub1[c], a1 = a0, a2 = a0, a3 = a0;
        for (int i = 0; i < 128; i++) {
            float4 f = *(const float4*)(sUinT + i*36 + rg*4);
            float w = sU1[i*64 + c];
            a0 += f.x*w; a1 += f.y*w; a2 += f.z*w; a3 += f.w*w;
        }
        *(float4*)(sHidT + c*36 + rg*4) =
            make_float4(gelu_f(a0), gelu_f(a1), gelu_f(a2), gelu_f(a3));
    }
    __syncthreads();

    // y = xs + hid @ u_w2 + u_b2
    {
        float a0 = sub2[c], a1 = a0, a2 = a0, a3 = a0;
        for (int i = 0; i < 64; i++) {
            float4 f = *(const float4*)(sHidT + i*36 + rg*4);
            float w = sU2[i*64 + c];
            a0 += f.x*w; a1 += f.y*w; a2 += f.z*w; a3 += f.w*w;
        }
        int r = rg * 4;
        sY[(r+0)*64 + c] = sUinT[c*36 + r+0] + a0;
        sY[(r+1)*64 + c] = sUinT[c*36 + r+1] + a1;
        sY[(r+2)*64 + c] = sUinT[c*36 + r+2] + a2;
        sY[(r+3)*64 + c] = sUinT[c*36 + r+3] + a3;
    }
    __syncthreads();

    // LN (32 rows, 16 lanes each)
    {
        int r = t >> 4, l = t & 15;
        float4 v = *(const float4*)&sY[r*64 + l*4];
        float s  = v.x + v.y + v.z + v.w;
        float ss = v.x*v.x + v.y*v.y + v.z*v.z + v.w*v.w;
        #pragma unroll
        for (int o = 1; o < 16; o <<= 1) {
            s  += __shfl_xor_sync(0xffffffffu, s,  o, 16);
            ss += __shfl_xor_sync(0xffffffffu, ss, o, 16);
        }
        if (l == 0) {
            float m = s * (1.f/64.f);
            float var = ss * (1.f/64.f) - m*m;
            smean[r] = m; sinv[r] = rsqrtf(var + 1e-5f);
        }
    }
    __syncthreads();
    for (int i = t; i < 2048; i += 512) {
        int r = i >> 6, cc = i & 63;
        g_x2[(rbase + r)*64 + cc] = (sY[i] - smean[r]) * sinv[r] * ssg[cc] + ssb[cc];
    }
}

// ---------------- K6: FFN + residual + LN -> d_out --------------------------
__global__ __launch_bounds__(512, 1) void ffn_kernel(
    const float* __restrict__ fw1, const float* __restrict__ fb1,
    const float* __restrict__ fw2, const float* __restrict__ fb2,
    const float* __restrict__ fg,  const float* __restrict__ fb,
    float* __restrict__ out)
{
    extern __shared__ float sm[];
    float* sW1 = sm;            // 64x256
    float* sW2 = sW1 + 16384;   // 256x64
    float* sb1 = sW2 + 16384;   // 256
    float* sb2 = sb1 + 256;     // 64
    float* sfg = sb2 + 64;
    float* sfb = sfg + 64;
    float* sXT = sfb + 64;      // [i<64][r<32] pad36 = 2304
    float* sHT = sXT + 2304;    // [i<256][r<32] pad36 = 9216
    float* sY  = sHT + 9216;    // 32x64
    float* smean = sY + 2048;   // 32
    float* sinv  = smean + 32;  // 32

    int t = threadIdx.x;  // 512
    for (int i = t; i < 16384; i += 512) { sW1[i] = fw1[i]; sW2[i] = fw2[i]; }
    if (t < 256) sb1[t] = fb1[t];
    if (t < 64) { sb2[t] = fb2[t]; sfg[t] = fg[t]; sfb[t] = fb[t]; }

    int rbase = blockIdx.x * 32;
    for (int idx = t; idx < 2048; idx += 512) {
        int c = idx & 63, r = idx >> 6;
        sXT[c*36 + r] = g_x2[(rbase + r)*64 + c];
    }
    __syncthreads();

    // H = gelu(X @ W1 + b1): 256 cols x 2 halves of 16 rows
    {
        int c = t & 255, half = t >> 8;
        float acc[16];
        #pragma unroll
        for (int r = 0; r < 16; r++) acc[r] = sb1[c];
        for (int i = 0; i < 64; i++) {
            float w = sW1[i*256 + c];
            const float4* xv = (const float4*)(sXT + i*36 + half*16);
            float4 a0 = xv[0], a1 = xv[1], a2 = xv[2], a3 = xv[3];
            acc[0]+=a0.x*w; acc[1]+=a0.y*w; acc[2]+=a0.z*w; acc[3]+=a0.w*w;
            acc[4]+=a1.x*w; acc[5]+=a1.y*w; acc[6]+=a1.z*w; acc[7]+=a1.w*w;
            acc[8]+=a2.x*w; acc[9]+=a2.y*w; acc[10]+=a2.z*w; acc[11]+=a2.w*w;
            acc[12]+=a3.x*w; acc[13]+=a3.y*w; acc[14]+=a3.z*w; acc[15]+=a3.w*w;
        }
        float4* hp = (float4*)(sHT + c*36 + half*16);
        hp[0] = make_float4(gelu_f(acc[0]),  gelu_f(acc[1]),  gelu_f(acc[2]),  gelu_f(acc[3]));
        hp[1] = make_float4(gelu_f(acc[4]),  gelu_f(acc[5]),  gelu_f(acc[6]),  gelu_f(acc[7]));
        hp[2] = make_float4(gelu_f(acc[8]),  gelu_f(acc[9]),  gelu_f(acc[10]), gelu_f(acc[11]));
        hp[3] = make_float4(gelu_f(acc[12]), gelu_f(acc[13]), gelu_f(acc[14]), gelu_f(acc[15]));
    }
    __syncthreads();

    // Y = X + H @ W2 + b2: 64 cols x 8 row-groups of 4
    {
        int c = t & 63, rg = t >> 6;
        float a0 = sb2[c], a1 = a0, a2 = a0, a3 = a0;
        for (int i = 0; i < 256; i++) {
            float4 f = *(const float4*)(sHT + i*36 + rg*4);
            float w = sW2[i*64 + c];
            a0 += f.x*w; a1 += f.y*w; a2 += f.z*w; a3 += f.w*w;
        }
        int r = rg * 4;
        sY[(r+0)*64 + c] = sXT[c*36 + r+0] + a0;
        sY[(r+1)*64 + c] = sXT[c*36 + r+1] + a1;
        sY[(r+2)*64 + c] = sXT[c*36 + r+2] + a2;
        sY[(r+3)*64 + c] = sXT[c*36 + r+3] + a3;
    }
    __syncthreads();

    // LN
    {
        int r = t >> 4, l = t & 15;
        float4 v = *(const float4*)&sY[r*64 + l*4];
        float s  = v.x + v.y + v.z + v.w;
        float ss = v.x*v.x + v.y*v.y + v.z*v.z + v.w*v.w;
        #pragma unroll
        for (int o = 1; o < 16; o <<= 1) {
            s  += __shfl_xor_sync(0xffffffffu, s,  o, 16);
            ss += __shfl_xor_sync(0xffffffffu, ss, o, 16);
        }
        if (l == 0) {
            float m = s * (1.f/64.f);
            float var = ss * (1.f/64.f) - m*m;
            smean[r] = m; sinv[r] = rsqrtf(var + 1e-5f);
        }
    }
    __syncthreads();
    for (int i = t; i < 2048; i += 512) {
        int r = i >> 6, cc = i & 63;
        out[(rbase + r)*64 + cc] = (sY[i] - smean[r]) * sinv[r] * sfg[cc] + sfb[cc];
    }
}

// ---------------- host launcher ---------------------------------------------
extern "C" void kernel_launch(void* const* d_in, const int* in_sizes, int n_in,
                              void* d_out, int out_size)
{
    (void)in_sizes; (void)n_in; (void)out_size;
    const float* x    = (const float*)d_in[0];
    const int*   ei   = (const int*)  d_in[1];
    const float* ea   = (const float*)d_in[2];
    const float* ipw  = (const float*)d_in[3];
    const float* ipb  = (const float*)d_in[4];
    const float* opw  = (const float*)d_in[5];
    const float* opb  = (const float*)d_in[6];
    const float* tng  = (const float*)d_in[7];
    const float* tnb  = (const float*)d_in[8];
    const float* ew1  = (const float*)d_in[9];
    const float* eb1  = (const float*)d_in[10];
    const float* ew2  = (const float*)d_in[11];
    const float* eb2  = (const float*)d_in[12];
    const float* mw1  = (const float*)d_in[13];
    const float* mb1  = (const float*)d_in[14];
    const float* mw2  = (const float*)d_in[15];
    const float* mb2  = (const float*)d_in[16];
    const float* uw1  = (const float*)d_in[17];
    const float* ub1  = (const float*)d_in[18];
    const float* uw2  = (const float*)d_in[19];
    const float* ub2  = (const float*)d_in[20];
    const float* sng  = (const float*)d_in[21];
    const float* snb  = (const float*)d_in[22];
    const float* fw1  = (const float*)d_in[23];
    const float* fb1  = (const float*)d_in[24];
    const float* fw2  = (const float*)d_in[25];
    const float* fb2  = (const float*)d_in[26];
    const float* fng  = (const float*)d_in[27];
    const float* fnb  = (const float*)d_in[28];
    float* out = (float*)d_out;

    const int SM_ATT = 24224 * 4;   // 96896
    const int SM_EE  = 12736 * 4;   // 50944
    const int SM_PQ  = 18688 * 4;   // 74752
    const int SM_UPD = 34464 * 4;   // 137856
    const int SM_FFN = 46848 * 4;   // 187392
    cudaFuncSetAttribute(attn_kernel,     cudaFuncAttributeMaxDynamicSharedMemorySize, SM_ATT);
    cudaFuncSetAttribute(edge_emb_kernel, cudaFuncAttributeMaxDynamicSharedMemorySize, SM_EE);
    cudaFuncSetAttribute(pq_kernel,       cudaFuncAttributeMaxDynamicSharedMemorySize, SM_PQ);
    cudaFuncSetAttribute(update_kernel,   cudaFuncAttributeMaxDynamicSharedMemorySize, SM_UPD);
    cudaFuncSetAttribute(ffn_kernel,      cudaFuncAttributeMaxDynamicSharedMemorySize, SM_FFN);

    csr_zero_kernel  <<<20, 256>>>();
    attn_kernel      <<<1250, 256, SM_ATT>>>(x, ipw, ipb, opw, opb, tng, tnb);
    csr_count_kernel <<<79, 256>>>(ei);
    csr_scan_kernel  <<<1, 1024>>>();
    csr_fill_kernel  <<<79, 256>>>(ei);
    edge_emb_kernel  <<<256, 128, SM_EE>>>(ea, ew1, eb1, ew2, eb2, mw1, mb1);
    pq_kernel        <<<5000, 512, SM_PQ>>>(mw1);
    aggr_kernel      <<<20000, 256>>>();
    update_kernel    <<<5000, 512, SM_UPD>>>(mw2, mb2, uw1, ub1, uw2, ub2, sng, snb);
    ffn_kernel       <<<5000, 512, SM_FFN>>>(fw1, fb1, fw2, fb2, fng, fnb, out);
}

// round 4
// speedup vs baseline: 1.8103x; 1.2774x over previous
#include <cuda_runtime.h>

// ---------------- problem constants ----------------
#define BB    2
#define SS    16
#define NN    5000
#define HH    64
#define EE    20000
#define BSS   (BB*SS)      // 32
#define BNN   (BB*NN)      // 10000
#define NROWS (BSS*NN)     // 160000

// ---------------- scratch (device globals) ----------------
__device__ __align__(16) float g_x1[NROWS*HH];
__device__ __align__(16) float g_x2[NROWS*HH];
__device__ __align__(16) float g_P [NROWS*128];
__device__ __align__(16) float g_Q [NROWS*128];
__device__ __align__(16) float g_R [EE*128];
__device__ __align__(16) float g_G [NROWS*128];
__device__ int  g_cnt[NN];
__device__ int  g_cur[NN];
__device__ int  g_off[NN+1];
__device__ int2 g_epk[EE];     // (src, e) sorted by dst

__device__ __forceinline__ float gelu_f(float v) {
    return 0.5f * v * (1.0f + erff(v * 0.70710678118654752f));
}

__device__ __forceinline__ float to_tf32(float x) {
    unsigned r;
    asm("cvt.rna.tf32.f32 %0, %1;" : "=r"(r) : "f"(x));
    return __uint_as_float(r);
}

// mma.m16n8k8 tf32: D(16x8) += A(16x8,row) * B(8x8,col)
// a0=(g,tig) a1=(g+8,tig) a2=(g,tig+4) a3=(g+8,tig+4)
// b0=(k=tig,n=g) b1=(k=tig+4,n=g)
// d0=(g,2tig) d1=(g,2tig+1) d2=(g+8,2tig) d3=(g+8,2tig+1)
__device__ __forceinline__ void mma_tf32(float4& d,
    float a0, float a1, float a2, float a3, float b0, float b1)
{
    asm volatile(
      "mma.sync.aligned.m16n8k8.row.col.f32.tf32.tf32.f32 "
      "{%0,%1,%2,%3},{%4,%5,%6,%7},{%8,%9},{%0,%1,%2,%3};\n"
      : "+f"(d.x), "+f"(d.y), "+f"(d.z), "+f"(d.w)
      : "r"(__float_as_uint(a0)), "r"(__float_as_uint(a1)),
        "r"(__float_as_uint(a2)), "r"(__float_as_uint(a3)),
        "r"(__float_as_uint(b0)), "r"(__float_as_uint(b1)));
}

// ---------------- CSR build ----------------
__global__ void csr_zero_kernel() {
    int i = blockIdx.x * blockDim.x + threadIdx.x;
    if (i < NN) g_cnt[i] = 0;
}
__global__ void csr_count_kernel(const int* __restrict__ ei) {
    int e = blockIdx.x * blockDim.x + threadIdx.x;
    if (e < EE) atomicAdd(&g_cnt[ei[EE + e]], 1);
}
__global__ void csr_scan_kernel() {
    __shared__ int sbuf[1024];
    __shared__ int scarry;
    int t = threadIdx.x;
    if (t == 0) scarry = 0;
    __syncthreads();
    for (int ch = 0; ch < 5; ch++) {
        int idx = ch * 1024 + t;
        int v = (idx < NN) ? g_cnt[idx] : 0;
        sbuf[t] = v; __syncthreads();
        for (int o = 1; o < 1024; o <<= 1) {
            int x = (t >= o) ? sbuf[t - o] : 0;
            __syncthreads();
            sbuf[t] += x;
            __syncthreads();
        }
        int incl = sbuf[t];
        int base = scarry;
        if (idx < NN) { int off = base + incl - v; g_off[idx] = off; g_cur[idx] = off; }
        __syncthreads();
        if (t == 1023) scarry = base + sbuf[1023];
        __syncthreads();
    }
    if (t == 0) g_off[NN] = scarry;
}
__global__ void csr_fill_kernel(const int* __restrict__ ei) {
    int e = blockIdx.x * blockDim.x + threadIdx.x;
    if (e < EE) {
        int dst = ei[EE + e];
        int pos = atomicAdd(&g_cur[dst], 1);
        g_epk[pos] = make_int2(ei[e], e);
    }
}

// ---------------- K1: temporal attention + residual + LN -------------------
__global__ __launch_bounds__(256, 2) void attn_kernel(
    const float* __restrict__ x,
    const float* __restrict__ Wi, const float* __restrict__ bi,
    const float* __restrict__ Wo, const float* __restrict__ bo,
    const float* __restrict__ tg, const float* __restrict__ tb)
{
    extern __shared__ float sm[];
    float* sWi   = sm;              // 64*192
    float* sWo   = sWi + 12288;     // 64*64
    float* sbi   = sWo + 4096;      // 192
    float* sbo   = sbi + 192;       // 64
    float* stg   = sbo + 64;        // 64
    float* stb   = stg + 64;        // 64
    float* sxtT  = stb + 64;        // 64*20 [c][s]
    float* sqkvT = sxtT + 1280;     // 192*20 [j][s]
    float* saoT  = sqkvT + 3840;    // 64*20 [d][s]
    float* sy    = saoT + 1280;     // 16*64
    float* smean = sy + 1024;       // 16
    float* sinv  = smean + 16;      // 16

    int t = threadIdx.x;
    for (int i = t; i < 12288; i += 256) sWi[i] = Wi[i];
    for (int i = t; i < 4096;  i += 256) sWo[i] = Wo[i];
    if (t < 192) sbi[t] = bi[t];
    if (t < 64) { sbo[t] = bo[t]; stg[t] = tg[t]; stb[t] = tb[t]; }
    __syncthreads();

    for (int u = 0; u < 8; u++) {
        int bn = blockIdx.x * 8 + u;
        int b = bn / NN, n = bn % NN;

        for (int i = t; i < 1024; i += 256) {
            int c = i & 63, s = i >> 6;
            sxtT[c*20 + s] = x[((b*SS + s)*NN + n)*HH + c];
        }
        __syncthreads();

        if (t < 192) {
            int j = t;
            float acc[16];
            #pragma unroll
            for (int r = 0; r < 16; r++) acc[r] = sbi[j];
            for (int i = 0; i < 64; i++) {
                float w = sWi[i*192 + j];
                const float4* xv = (const float4*)(sxtT + i*20);
                float4 a0 = xv[0], a1 = xv[1], a2 = xv[2], a3 = xv[3];
                acc[0]+=a0.x*w; acc[1]+=a0.y*w; acc[2]+=a0.z*w; acc[3]+=a0.w*w;
                acc[4]+=a1.x*w; acc[5]+=a1.y*w; acc[6]+=a1.z*w; acc[7]+=a1.w*w;
                acc[8]+=a2.x*w; acc[9]+=a2.y*w; acc[10]+=a2.z*w; acc[11]+=a2.w*w;
                acc[12]+=a3.x*w; acc[13]+=a3.y*w; acc[14]+=a3.z*w; acc[15]+=a3.w*w;
            }
            float4* qv = (float4*)(sqkvT + j*20);
            qv[0] = make_float4(acc[0],acc[1],acc[2],acc[3]);
            qv[1] = make_float4(acc[4],acc[5],acc[6],acc[7]);
            qv[2] = make_float4(acc[8],acc[9],acc[10],acc[11]);
            qv[3] = make_float4(acc[12],acc[13],acc[14],acc[15]);
        }
        __syncthreads();

        if (t < 64) {
            int h = t >> 4, q = t & 15;
            float sc[16];
            #pragma unroll
            for (int k = 0; k < 16; k++) sc[k] = 0.f;
            #pragma unroll
            for (int d = 0; d < 16; d++) {
                float qv = sqkvT[(h*16 + d)*20 + q];
                const float4* kk = (const float4*)(sqkvT + (64 + h*16 + d)*20);
                float4 k0 = kk[0], k1 = kk[1], k2 = kk[2], k3 = kk[3];
                sc[0]+=qv*k0.x; sc[1]+=qv*k0.y; sc[2]+=qv*k0.z; sc[3]+=qv*k0.w;
                sc[4]+=qv*k1.x; sc[5]+=qv*k1.y; sc[6]+=qv*k1.z; sc[7]+=qv*k1.w;
                sc[8]+=qv*k2.x; sc[9]+=qv*k2.y; sc[10]+=qv*k2.z; sc[11]+=qv*k2.w;
                sc[12]+=qv*k3.x; sc[13]+=qv*k3.y; sc[14]+=qv*k3.z; sc[15]+=qv*k3.w;
            }
            float mx = -1e30f;
            #pragma unroll
            for (int k = 0; k < 16; k++) { sc[k] *= 0.25f; mx = fmaxf(mx, sc[k]); }
            float den = 0.f;
            #pragma unroll
            for (int k = 0; k < 16; k++) { sc[k] = expf(sc[k] - mx); den += sc[k]; }
            float inv = 1.f / den;
            #pragma unroll
            for (int d = 0; d < 16; d++) {
                const float4* vv = (const float4*)(sqkvT + (128 + h*16 + d)*20);
                float4 v0 = vv[0], v1 = vv[1], v2 = vv[2], v3 = vv[3];
                float o = sc[0]*v0.x + sc[1]*v0.y + sc[2]*v0.z + sc[3]*v0.w
                        + sc[4]*v1.x + sc[5]*v1.y + sc[6]*v1.z + sc[7]*v1.w
                        + sc[8]*v2.x + sc[9]*v2.y + sc[10]*v2.z + sc[11]*v2.w
                        + sc[12]*v3.x + sc[13]*v3.y + sc[14]*v3.z + sc[15]*v3.w;
                saoT[(h*16 + d)*20 + q] = o * inv;
            }
        }
        __syncthreads();

        {
            int c = t & 63, rg = t >> 6;
            float a0 = sbo[c], a1 = a0, a2 = a0, a3 = a0;
            for (int i = 0; i < 64; i++) {
                float4 f = *(const float4*)(saoT + i*20 + rg*4);
                float w = sWo[i*64 + c];
                a0 += f.x*w; a1 += f.y*w; a2 += f.z*w; a3 += f.w*w;
            }
            int r = rg * 4;
            sy[(r+0)*64 + c] = sxtT[c*20 + r+0] + a0;
            sy[(r+1)*64 + c] = sxtT[c*20 + r+1] + a1;
            sy[(r+2)*64 + c] = sxtT[c*20 + r+2] + a2;
            sy[(r+3)*64 + c] = sxtT[c*20 + r+3] + a3;
        }
        __syncthreads();

        {
            int r = t >> 4, l = t & 15;
            float4 v = *(const float4*)&sy[r*64 + l*4];
            float s  = v.x + v.y + v.z + v.w;
            float ss = v.x*v.x + v.y*v.y + v.z*v.z + v.w*v.w;
            #pragma unroll
            for (int o = 1; o < 16; o <<= 1) {
                s  += __shfl_xor_sync(0xffffffffu, s,  o, 16);
                ss += __shfl_xor_sync(0xffffffffu, ss, o, 16);
            }
            if (l == 0) {
                float m = s * (1.f/64.f);
                float var = ss * (1.f/64.f) - m*m;
                smean[r] = m; sinv[r] = rsqrtf(var + 1e-5f);
            }
        }
        __syncthreads();
        for (int i = t; i < 1024; i += 256) {
            int r = i >> 6, c = i & 63;
            g_x1[((b*SS + r)*NN + n)*HH + c] = (sy[i] - smean[r]) * sinv[r] * stg[c] + stb[c];
        }
        __syncthreads();
    }
}

// ---------------- K2: edge embedding -> R ---------------------
__global__ void edge_emb_kernel(const float* __restrict__ ea,
                                const float* __restrict__ ew1, const float* __restrict__ eb1,
                                const float* __restrict__ ew2, const float* __restrict__ eb2,
                                const float* __restrict__ mw1, const float* __restrict__ mb1)
{
    extern __shared__ float sm[];
    float* sEw2 = sm;            // 64*64
    float* sWc  = sEw2 + 4096;   // 64*128
    float* sew1 = sWc + 8192;
    float* seb1 = sew1 + 64;
    float* seb2 = seb1 + 64;
    float* smb1 = seb2 + 64;     // 128
    float* semb = smb1 + 128;    // 64
    float* semb2= semb + 64;     // 64

    int t = threadIdx.x;   // 128
    for (int i = t; i < 4096; i += 128) sEw2[i] = ew2[i];
    for (int i = t; i < 8192; i += 128) sWc[i]  = mw1[128*128 + i];
    if (t < 64) { sew1[t] = ew1[t]; seb1[t] = eb1[t]; seb2[t] = eb2[t]; }
    smb1[t] = mb1[t];
    __syncthreads();

    for (int e = blockIdx.x; e < EE; e += gridDim.x) {
        if (t < 64) semb[t] = gelu_f(ea[e] * sew1[t] + seb1[t]);
        __syncthreads();
        if (t < 64) {
            float a = seb2[t];
            #pragma unroll 8
            for (int i = 0; i < 64; i++) a += semb[i] * sEw2[i*64 + t];
            semb2[t] = a;
        }
        __syncthreads();
        {
            float a = smb1[t];
            #pragma unroll 8
            for (int i = 0; i < 64; i++) a += semb2[i] * sWc[i*128 + t];
            g_R[e*128 + t] = a;
        }
        __syncthreads();
    }
}

// ---------------- K3: P,Q node GEMM via tf32 MMA ----------------
// X[32x64] @ W[64x256] -> [P | Q]. 512 thr, 16 warps: (mt 2) x (ngroup 8, 4 ntiles)
__global__ __launch_bounds__(512, 1) void pq_kernel(const float* __restrict__ mw1)
{
    extern __shared__ float sm[];
    float* sWf = sm;           // 64x256 in B-fragment order (KT=8, NT=32)
    float* sA  = sm + 16384;   // 32 x 68 (tf32)

    int t = threadIdx.x;
    for (int idx = t; idx < 16384; idx += 512) {
        int k = idx >> 8, c = idx & 255;
        float w = (c < 128) ? (mw1[k*128 + c] - mw1[(64+k)*128 + c])
                            :  mw1[(64+k)*128 + (c-128)];
        int kt = k >> 3, kk = k & 7, j = kk >> 2, tg = kk & 3;
        int nt = c >> 3, gg = c & 7;
        sWf[((((kt<<5) + nt)<<5) + (gg<<2) + tg)*2 + j] = to_tf32(w);
    }
    int rbase = blockIdx.x * 32;
    for (int idx = t; idx < 2048; idx += 512) {
        int r = idx >> 6, c = idx & 63;
        sA[r*68 + c] = to_tf32(g_x1[(rbase + r)*64 + c]);
    }
    __syncthreads();

    int w = t >> 5, lane = t & 31, g = lane >> 2, tg = lane & 3;
    int mt = w >> 3, ng = w & 7;
    float4 d[4];
    #pragma unroll
    for (int i = 0; i < 4; i++) d[i] = make_float4(0.f, 0.f, 0.f, 0.f);

    #pragma unroll
    for (int kt = 0; kt < 8; kt++) {
        const float* Ab = sA + (mt*16)*68 + kt*8;
        float a0 = Ab[g*68 + tg],     a1 = Ab[(g+8)*68 + tg];
        float a2 = Ab[g*68 + tg + 4], a3 = Ab[(g+8)*68 + tg + 4];
        #pragma unroll
        for (int i = 0; i < 4; i++) {
            int nt = ng*4 + i;
            float2 b = *(const float2*)&sWf[((((kt<<5) + nt)<<5) + lane)*2];
            mma_tf32(d[i], a0, a1, a2, a3, b.x, b.y);
        }
    }

    #pragma unroll
    for (int i = 0; i < 4; i++) {
        int nt = ng*4 + i;
        int col = nt*8 + 2*tg;
        float* base = (col < 128) ? (g_P + rbase*128 + col)
                                  : (g_Q + rbase*128 + (col - 128));
        int r0 = mt*16 + g;
        *(float2*)&base[r0*128]     = make_float2(d[i].x, d[i].y);
        *(float2*)&base[(r0+8)*128] = make_float2(d[i].z, d[i].w);
    }
}

// ---------------- K4: CSR gather aggregation (no atomics) -------------------
__global__ __launch_bounds__(256) void aggr_kernel()
{
    int w = (blockIdx.x * 256 + threadIdx.x) >> 5;   // 0..159999
    int lane = threadIdx.x & 31;
    int b = w & 31, dst = w >> 5;
    int row = b * NN + dst;
    float4 q = ((const float4*)g_Q)[row*32 + lane];
    float4 acc = make_float4(0.f, 0.f, 0.f, 0.f);
    int s = g_off[dst], e = g_off[dst+1];
    for (int k = s; k < e; k++) {
        int2 pe = g_epk[k];
        float4 p = ((const float4*)g_P)[(b*NN + pe.x)*32 + lane];
        float4 r = ((const float4*)g_R)[pe.y*32 + lane];
        acc.x += gelu_f(p.x + q.x + r.x);
        acc.y += gelu_f(p.y + q.y + r.y);
        acc.z += gelu_f(p.z + q.z + r.z);
        acc.w += gelu_f(p.w + q.w + r.w);
    }
    ((float4*)g_G)[row*32 + lane] = acc;
}

// ---------------- K5: update MLP via tf32 MMA + residual + LN ----------------
__global__ __launch_bounds__(512, 1) void update_kernel(
    const float* __restrict__ mw2, const float* __restrict__ mb2,
    const float* __restrict__ uw1, const float* __restrict__ ub1,
    const float* __restrict__ uw2, const float* __restrict__ ub2,
    const float* __restrict__ sg,  const float* __restrict__ sb)
{
    extern __shared__ float sm[];
    float* sW2f = sm;               // mw2 128x64 frag (KT=16,NT=8): 8192
    float* sU1f = sW2f + 8192;      // uw1 128x64 frag: 8192
    float* sU2f = sU1f + 8192;      // uw2 64x64 frag (KT=8,NT=8): 4096
    float* sG   = sU2f + 4096;      // 32 x 132 tf32
    float* sUin = sG + 4224;        // 32 x 132 tf32
    float* sHid = sUin + 4224;      // 32 x 68 tf32
    float* sXr  = sHid + 2176;      // 32 x 64 fp32
    float* sY   = sXr + 2048;       // 32 x 64
    float* smb2 = sY + 2048;        // 64
    float* sub1 = smb2 + 64;
    float* sub2 = sub1 + 64;
    float* ssg  = sub2 + 64;
    float* ssb  = ssg + 64;
    float* sdeg = ssb + 64;         // 32
    float* smean= sdeg + 32;        // 32
    float* sinv = smean + 32;       // 32

    int t = threadIdx.x;
    // weights (128x64): KT=16
    for (int idx = t; idx < 8192; idx += 512) {
        int k = idx >> 6, c = idx & 63;
        int kt = k >> 3, kk = k & 7, j = kk >> 2, tg = kk & 3;
        int nt = c >> 3, gg = c & 7;
        int fi = ((((kt<<3) + nt)<<5) + (gg<<2) + tg)*2 + j;
        sW2f[fi] = to_tf32(mw2[idx]);
        sU1f[fi] = to_tf32(uw1[idx]);
    }
    // uw2 (64x64): KT=8
    for (int idx = t; idx < 4096; idx += 512) {
        int k = idx >> 6, c = idx & 63;
        int kt = k >> 3, kk = k & 7, j = kk >> 2, tg = kk & 3;
        int nt = c >> 3, gg = c & 7;
        sU2f[((((kt<<3) + nt)<<5) + (gg<<2) + tg)*2 + j] = to_tf32(uw2[idx]);
    }
    if (t < 64) { smb2[t] = mb2[t]; sub1[t] = ub1[t]; sub2[t] = ub2[t]; ssg[t] = sg[t]; ssb[t] = sb[t]; }

    int rbase = blockIdx.x * 32;
    for (int idx = t; idx < 4096; idx += 512) {
        int c = idx & 127, r = idx >> 7;
        sG[r*132 + c] = to_tf32(g_G[(rbase + r)*128 + c]);
    }
    for (int idx = t; idx < 2048; idx += 512) {
        int c = idx & 63, r = idx >> 6;
        float v = g_x1[(rbase + r)*64 + c];
        sXr[r*64 + c] = v;
        sUin[r*132 + c] = to_tf32(v);
    }
    if (t < 32) {
        int n = (rbase + t) % NN;
        sdeg[t] = (float)(g_off[n+1] - g_off[n]);
    }
    __syncthreads();

    int w = t >> 5, lane = t & 31, g = lane >> 2, tg = lane & 3;
    int mt = w >> 3, nt = w & 7;
    int col = nt*8 + 2*tg;
    int r0 = mt*16 + g;

    // Stage0: aggr = G @ mw2 + deg*mb2 -> sUin[:, 64+..] (tf32)
    {
        float4 d = make_float4(sdeg[r0]*smb2[col],   sdeg[r0]*smb2[col+1],
                               sdeg[r0+8]*smb2[col], sdeg[r0+8]*smb2[col+1]);
        #pragma unroll
        for (int kt = 0; kt < 16; kt++) {
            const float* Ab = sG + (mt*16)*132 + kt*8;
            float a0 = Ab[g*132 + tg],     a1 = Ab[(g+8)*132 + tg];
            float a2 = Ab[g*132 + tg + 4], a3 = Ab[(g+8)*132 + tg + 4];
            float2 b = *(const float2*)&sW2f[((((kt<<3) + nt)<<5) + lane)*2];
            mma_tf32(d, a0, a1, a2, a3, b.x, b.y);
        }
        *(float2*)&sUin[r0*132 + 64 + col]     = make_float2(to_tf32(d.x), to_tf32(d.y));
        *(float2*)&sUin[(r0+8)*132 + 64 + col] = make_float2(to_tf32(d.z), to_tf32(d.w));
    }
    __syncthreads();

    // Stage1: hid = gelu(Uin @ uw1 + ub1) -> sHid (tf32)
    {
        float4 d = make_float4(sub1[col], sub1[col+1], sub1[col], sub1[col+1]);
        #pragma unroll
        for (int kt = 0; kt < 16; kt++) {
            const float* Ab = sUin + (mt*16)*132 + kt*8;
            float a0 = Ab[g*132 + tg],     a1 = Ab[(g+8)*132 + tg];
            float a2 = Ab[g*132 + tg + 4], a3 = Ab[(g+8)*132 + tg + 4];
            float2 b = *(const float2*)&sU1f[((((kt<<3) + nt)<<5) + lane)*2];
            mma_tf32(d, a0, a1, a2, a3, b.x, b.y);
        }
        *(float2*)&sHid[r0*68 + col]     = make_float2(to_tf32(gelu_f(d.x)), to_tf32(gelu_f(d.y)));
        *(float2*)&sHid[(r0+8)*68 + col] = make_float2(to_tf32(gelu_f(d.z)), to_tf32(gelu_f(d.w)));
    }
    __syncthreads();

    // Stage2: y = xs + hid @ uw2 + ub2 -> sY
    {
        float4 d = make_float4(sub2[col], sub2[col+1], sub2[col], sub2[col+1]);
        #pragma unroll
        for (int kt = 0; kt < 8; kt++) {
            const float* Ab = sHid + (mt*16)*68 + kt*8;
            float a0 = Ab[g*68 + tg],     a1 = Ab[(g+8)*68 + tg];
            float a2 = Ab[g*68 + tg + 4], a3 = Ab[(g+8)*68 + tg + 4];
            float2 b = *(const float2*)&sU2f[((((kt<<3) + nt)<<5) + lane)*2];
            mma_tf32(d, a0, a1, a2, a3, b.x, b.y);
        }
        sY[r0*64 + col]       = sXr[r0*64 + col]       + d.x;
        sY[r0*64 + col+1]     = sXr[r0*64 + col+1]     + d.y;
        sY[(r0+8)*64 + col]   = sXr[(r0+8)*64 + col]   + d.z;
        sY[(r0+8)*64 + col+1] = sXr[(r0+8)*64 + col+1] + d.w;
    }
    __syncthreads();

    // LN
    {
        int r = t >> 4, l = t & 15;
        float4 v = *(const float4*)&sY[r*64 + l*4];
        float s  = v.x + v.y + v.z + v.w;
        float ss = v.x*v.x + v.y*v.y + v.z*v.z + v.w*v.w;
        #pragma unroll
        for (int o = 1; o < 16; o <<= 1) {
            s  += __shfl_xor_sync(0xffffffffu, s,  o, 16);
            ss += __shfl_xor_sync(0xffffffffu, ss, o, 16);
        }
        if (l == 0) {
            float m = s * (1.f/64.f);
            float var = ss * (1.f/64.f) - m*m;
            smean[r] = m; sinv[r] = rsqrtf(var + 1e-5f);
        }
    }
    __syncthreads();
    for (int i = t; i < 2048; i += 512) {
        int r = i >> 6, cc = i & 63;
        g_x2[(rbase + r)*64 + cc] = (sY[i] - smean[r]) * sinv[r] * ssg[cc] + ssb[cc];
    }
}

// ---------------- K6: FFN via tf32 MMA + residual + LN -> d_out --------------
__global__ __launch_bounds__(512, 1) void ffn_kernel(
    const float* __restrict__ fw1, const float* __restrict__ fb1,
    const float* __restrict__ fw2, const float* __restrict__ fb2,
    const float* __restrict__ fg,  const float* __restrict__ fb,
    float* __restrict__ out)
{
    extern __shared__ float sm[];
    float* sW1f = sm;               // fw1 64x256 frag (KT=8,NT=32): 16384
    float* sW2f = sW1f + 16384;     // fw2 256x64 frag (KT=32,NT=8): 16384
    float* sA   = sW2f + 16384;     // X 32 x 68 tf32
    float* sH   = sA + 2176;        // H 32 x 260 tf32
    float* sXr  = sH + 8320;        // 32 x 64 fp32
    float* sY   = sXr + 2048;       // 32 x 64
    float* sb1  = sY + 2048;        // 256
    float* sb2  = sb1 + 256;        // 64
    float* sfg  = sb2 + 64;
    float* sfb  = sfg + 64;
    float* smean= sfb + 64;         // 32
    float* sinv = smean + 32;       // 32

    int t = threadIdx.x;
    // fw1 (64x256): KT=8, NT=32
    for (int idx = t; idx < 16384; idx += 512) {
        int k = idx >> 8, c = idx & 255;
        int kt = k >> 3, kk = k & 7, j = kk >> 2, tg = kk & 3;
        int nt = c >> 3, gg = c & 7;
        sW1f[((((kt<<5) + nt)<<5) + (gg<<2) + tg)*2 + j] = to_tf32(fw1[idx]);
    }
    // fw2 (256x64): KT=32, NT=8
    for (int idx = t; idx < 16384; idx += 512) {
        int k = idx >> 6, c = idx & 63;
        int kt = k >> 3, kk = k & 7, j = kk >> 2, tg = kk & 3;
        int nt = c >> 3, gg = c & 7;
        sW2f[((((kt<<3) + nt)<<5) + (gg<<2) + tg)*2 + j] = to_tf32(fw2[idx]);
    }
    if (t < 256) sb1[t] = fb1[t];
    if (t < 64) { sb2[t] = fb2[t]; sfg[t] = fg[t]; sfb[t] = fb[t]; }

    int rbase = blockIdx.x * 32;
    for (int idx = t; idx < 2048; idx += 512) {
        int c = idx & 63, r = idx >> 6;
        float v = g_x2[(rbase + r)*64 + c];
        sXr[r*64 + c] = v;
        sA[r*68 + c] = to_tf32(v);
    }
    __syncthreads();

    int w = t >> 5, lane = t & 31, g = lane >> 2, tg = lane & 3;

    // Stage1: H = gelu(X @ W1 + b1), N=256: warp = (mt, 4 ntiles)
    {
        int mt = w >> 3, ng = w & 7;
        float4 d[4];
        #pragma unroll
        for (int i = 0; i < 4; i++) {
            int col = (ng*4 + i)*8 + 2*tg;
            d[i] = make_float4(sb1[col], sb1[col+1], sb1[col], sb1[col+1]);
        }
        #pragma unroll
        for (int kt = 0; kt < 8; kt++) {
            const float* Ab = sA + (mt*16)*68 + kt*8;
            float a0 = Ab[g*68 + tg],     a1 = Ab[(g+8)*68 + tg];
            float a2 = Ab[g*68 + tg + 4], a3 = Ab[(g+8)*68 + tg + 4];
            #pragma unroll
            for (int i = 0; i < 4; i++) {
                int nt = ng*4 + i;
                float2 b = *(const float2*)&sW1f[((((kt<<5) + nt)<<5) + lane)*2];
                mma_tf32(d[i], a0, a1, a2, a3, b.x, b.y);
            }
        }
        int r0 = mt*16 + g;
        #pragma unroll
        for (int i = 0; i < 4; i++) {
            int col = (ng*4 + i)*8 + 2*tg;
            *(float2*)&sH[r0*260 + col]     = make_float2(to_tf32(gelu_f(d[i].x)), to_tf32(gelu_f(d[i].y)));
            *(float2*)&sH[(r0+8)*260 + col] = make_float2(to_tf32(gelu_f(d[i].z)), to_tf32(gelu_f(d[i].w)));
        }
    }
    __syncthreads();

    // Stage2: Y = X + H @ W2 + b2, K=256: warp = (mt, nt)
    {
        int mt = w >> 3, nt = w & 7;
        int col = nt*8 + 2*tg;
        int r0 = mt*16 + g;
        float4 d = make_float4(sb2[col], sb2[col+1], sb2[col], sb2[col+1]);
        #pragma unroll
        for (int kt = 0; kt < 32; kt++) {
            const float* Ab = sH + (mt*16)*260 + kt*8;
            float a0 = Ab[g*260 + tg],     a1 = Ab[(g+8)*260 + tg];
            float a2 = Ab[g*260 + tg + 4], a3 = Ab[(g+8)*260 + tg + 4];
            float2 b = *(const float2*)&sW2f[((((kt<<3) + nt)<<5) + lane)*2];
            mma_tf32(d, a0, a1, a2, a3, b.x, b.y);
        }
        sY[r0*64 + col]       = sXr[r0*64 + col]       + d.x;
        sY[r0*64 + col+1]     = sXr[r0*64 + col+1]     + d.y;
        sY[(r0+8)*64 + col]   = sXr[(r0+8)*64 + col]   + d.z;
        sY[(r0+8)*64 + col+1] = sXr[(r0+8)*64 + col+1] + d.w;
    }
    __syncthreads();

    // LN
    {
        int r = t >> 4, l = t & 15;
        float4 v = *(const float4*)&sY[r*64 + l*4];
        float s  = v.x + v.y + v.z + v.w;
        float ss = v.x*v.x + v.y*v.y + v.z*v.z + v.w*v.w;
        #pragma unroll
        for (int o = 1; o < 16; o <<= 1) {
            s  += __shfl_xor_sync(0xffffffffu, s,  o, 16);
            ss += __shfl_xor_sync(0xffffffffu, ss, o, 16);
        }
        if (l == 0) {
            float m = s * (1.f/64.f);
            float var = ss * (1.f/64.f) - m*m;
            smean[r] = m; sinv[r] = rsqrtf(var + 1e-5f);
        }
    }
    __syncthreads();
    for (int i = t; i < 2048; i += 512) {
        int r = i >> 6, cc = i & 63;
        out[(rbase + r)*64 + cc] = (sY[i] - smean[r]) * sinv[r] * sfg[cc] + sfb[cc];
    }
}

// ---------------- host launcher ---------------------------------------------
extern "C" void kernel_launch(void* const* d_in, const int* in_sizes, int n_in,
                              void* d_out, int out_size)
{
    (void)in_sizes; (void)n_in; (void)out_size;
    const float* x    = (const float*)d_in[0];
    const int*   ei   = (const int*)  d_in[1];
    const float* ea   = (const float*)d_in[2];
    const float* ipw  = (const float*)d_in[3];
    const float* ipb  = (const float*)d_in[4];
    const float* opw  = (const float*)d_in[5];
    const float* opb  = (const float*)d_in[6];
    const float* tng  = (const float*)d_in[7];
    const float* tnb  = (const float*)d_in[8];
    const float* ew1  = (const float*)d_in[9];
    const float* eb1  = (const float*)d_in[10];
    const float* ew2  = (const float*)d_in[11];
    const float* eb2  = (const float*)d_in[12];
    const float* mw1  = (const float*)d_in[13];
    const float* mb1  = (const float*)d_in[14];
    const float* mw2  = (const float*)d_in[15];
    const float* mb2  = (const float*)d_in[16];
    const float* uw1  = (const float*)d_in[17];
    const float* ub1  = (const float*)d_in[18];
    const float* uw2  = (const float*)d_in[19];
    const float* ub2  = (const float*)d_in[20];
    const float* sng  = (const float*)d_in[21];
    const float* snb  = (const float*)d_in[22];
    const float* fw1  = (const float*)d_in[23];
    const float* fb1  = (const float*)d_in[24];
    const float* fw2  = (const float*)d_in[25];
    const float* fb2  = (const float*)d_in[26];
    const float* fng  = (const float*)d_in[27];
    const float* fnb  = (const float*)d_in[28];
    float* out = (float*)d_out;

    const int SM_ATT = 24224 * 4;
    const int SM_EE  = 12736 * 4;
    const int SM_PQ  = (16384 + 2176) * 4;                            // 74240
    const int SM_UPD = (8192+8192+4096+4224+4224+2176+2048+2048+64*5+32*3) * 4; // ~142k
    const int SM_FFN = (16384+16384+2176+8320+2048+2048+256+64*3+32*2) * 4;     // ~192k
    cudaFuncSetAttribute(attn_kernel,     cudaFuncAttributeMaxDynamicSharedMemorySize, SM_ATT);
    cudaFuncSetAttribute(edge_emb_kernel, cudaFuncAttributeMaxDynamicSharedMemorySize, SM_EE);
    cudaFuncSetAttribute(pq_kernel,       cudaFuncAttributeMaxDynamicSharedMemorySize, SM_PQ);
    cudaFuncSetAttribute(update_kernel,   cudaFuncAttributeMaxDynamicSharedMemorySize, SM_UPD);
    cudaFuncSetAttribute(ffn_kernel,      cudaFuncAttributeMaxDynamicSharedMemorySize, SM_FFN);

    csr_zero_kernel  <<<20, 256>>>();
    attn_kernel      <<<1250, 256, SM_ATT>>>(x, ipw, ipb, opw, opb, tng, tnb);
    csr_count_kernel <<<79, 256>>>(ei);
    csr_scan_kernel  <<<1, 1024>>>();
    csr_fill_kernel  <<<79, 256>>>(ei);
    edge_emb_kernel  <<<256, 128, SM_EE>>>(ea, ew1, eb1, ew2, eb2, mw1, mb1);
    pq_kernel        <<<5000, 512, SM_PQ>>>(mw1);
    aggr_kernel      <<<20000, 256>>>();
    update_kernel    <<<5000, 512, SM_UPD>>>(mw2, mb2, uw1, ub1, uw2, ub2, sng, snb);
    ffn_kernel       <<<5000, 512, SM_FFN>>>(fw1, fb1, fw2, fb2, fng, fnb, out);
}

// round 5
// speedup vs baseline: 1.9770x; 1.0921x over previous
#include <cuda_runtime.h>

// ---------------- problem constants ----------------
#define BB    2
#define SS    16
#define NN    5000
#define HH    64
#define EE    20000
#define BSS   (BB*SS)      // 32
#define BNN   (BB*NN)      // 10000
#define NROWS (BSS*NN)     // 160000

// ---------------- scratch (device globals) ----------------
__device__ __align__(16) float g_x1[NROWS*HH];
__device__ __align__(16) float g_x2[NROWS*HH];
__device__ __align__(16) float g_P [NROWS*128];
__device__ __align__(16) float g_Q [NROWS*128];
__device__ __align__(16) float g_R [EE*128];
__device__ __align__(16) float g_G [NROWS*128];
__device__ int  g_cnt[NN];
__device__ int  g_cur[NN];
__device__ int  g_off[NN+1];
__device__ int2 g_epk[EE];     // (src, e) sorted by dst

__device__ __forceinline__ float gelu_f(float v) {
    return 0.5f * v * (1.0f + erff(v * 0.70710678118654752f));
}

__device__ __forceinline__ float to_tf32(float x) {
    unsigned r;
    asm("cvt.rna.tf32.f32 %0, %1;" : "=r"(r) : "f"(x));
    return __uint_as_float(r);
}

// mma.m16n8k8 tf32: D(16x8) += A(16x8,row) * B(8x8,col)
__device__ __forceinline__ void mma_tf32(float4& d,
    float a0, float a1, float a2, float a3, float b0, float b1)
{
    asm volatile(
      "mma.sync.aligned.m16n8k8.row.col.f32.tf32.tf32.f32 "
      "{%0,%1,%2,%3},{%4,%5,%6,%7},{%8,%9},{%0,%1,%2,%3};\n"
      : "+f"(d.x), "+f"(d.y), "+f"(d.z), "+f"(d.w)
      : "r"(__float_as_uint(a0)), "r"(__float_as_uint(a1)),
        "r"(__float_as_uint(a2)), "r"(__float_as_uint(a3)),
        "r"(__float_as_uint(b0)), "r"(__float_as_uint(b1)));
}

// ---------------- CSR build ----------------
__global__ void csr_zero_kernel() {
    int i = blockIdx.x * blockDim.x + threadIdx.x;
    if (i < NN) g_cnt[i] = 0;
}
__global__ void csr_count_kernel(const int* __restrict__ ei) {
    int e = blockIdx.x * blockDim.x + threadIdx.x;
    if (e < EE) atomicAdd(&g_cnt[ei[EE + e]], 1);
}
__global__ void csr_scan_kernel() {
    __shared__ int sbuf[1024];
    __shared__ int scarry;
    int t = threadIdx.x;
    if (t == 0) scarry = 0;
    __syncthreads();
    for (int ch = 0; ch < 5; ch++) {
        int idx = ch * 1024 + t;
        int v = (idx < NN) ? g_cnt[idx] : 0;
        sbuf[t] = v; __syncthreads();
        for (int o = 1; o < 1024; o <<= 1) {
            int x = (t >= o) ? sbuf[t - o] : 0;
            __syncthreads();
            sbuf[t] += x;
            __syncthreads();
        }
        int incl = sbuf[t];
        int base = scarry;
        if (idx < NN) { int off = base + incl - v; g_off[idx] = off; g_cur[idx] = off; }
        __syncthreads();
        if (t == 1023) scarry = base + sbuf[1023];
        __syncthreads();
    }
    if (t == 0) g_off[NN] = scarry;
}
__global__ void csr_fill_kernel(const int* __restrict__ ei) {
    int e = blockIdx.x * blockDim.x + threadIdx.x;
    if (e < EE) {
        int dst = ei[EE + e];
        int pos = atomicAdd(&g_cur[dst], 1);
        g_epk[pos] = make_int2(ei[e], e);
    }
}

// ---------------- K1: temporal attention via tf32 MMA + residual + LN -------
// 512 thr, 4 (b,n) sequences per block (M=64). qkv & out-proj on tensor pipe,
// softmax core exact fp32 scalar.
__global__ __launch_bounds__(512, 1) void attn_kernel(
    const float* __restrict__ x,
    const float* __restrict__ Wi, const float* __restrict__ bi,
    const float* __restrict__ Wo, const float* __restrict__ bo,
    const float* __restrict__ tg_, const float* __restrict__ tb_)
{
    extern __shared__ float sm[];
    float* sWif = sm;            // 12288: Wi frag (KT=8, NT=24)
    float* sWof = sWif + 12288;  // 4096 : Wo frag (KT=8, NT=8)
    float* sbi  = sWof + 4096;   // 192
    float* sbo  = sbi + 192;     // 64
    float* stg  = sbo + 64;      // 64
    float* stb  = stg + 64;      // 64
    float* sX   = stb + 64;      // 64x68 tf32
    float* sXr  = sX + 4352;     // 64x64 fp32 (residual)
    float* sqkvT= sXr + 4096;    // [seq<4][j<192][s<16] pad20 = 15360
    float* saoT = sqkvT + 15360; // [seq<4][d<64][q<16] pad20 = 5120
    float* sY   = saoT + 5120;   // 64x64
    float* smean= sY + 4096;     // 64
    float* sinv = smean + 64;    // 64

    int t = threadIdx.x;
    // Wi (64x192) -> B-fragment order, NT=24
    for (int idx = t; idx < 12288; idx += 512) {
        int k = idx / 192, c = idx % 192;
        int kt = k >> 3, kk = k & 7, j = kk >> 2, tgi = kk & 3;
        int nt = c >> 3, gg = c & 7;
        sWif[((kt*24 + nt)*32 + (gg<<2) + tgi)*2 + j] = to_tf32(Wi[idx]);
    }
    // Wo (64x64) -> B-fragment order, NT=8
    for (int idx = t; idx < 4096; idx += 512) {
        int k = idx >> 6, c = idx & 63;
        int kt = k >> 3, kk = k & 7, j = kk >> 2, tgi = kk & 3;
        int nt = c >> 3, gg = c & 7;
        sWof[((((kt<<3) + nt)<<5) + (gg<<2) + tgi)*2 + j] = to_tf32(Wo[idx]);
    }
    if (t < 192) sbi[t] = bi[t];
    if (t < 64) { sbo[t] = bo[t]; stg[t] = tg_[t]; stb[t] = tb_[t]; }

    int bn0 = blockIdx.x * 4;
    for (int idx = t; idx < 4096; idx += 512) {
        int row = idx >> 6, c = idx & 63;
        int seq = row >> 4, s = row & 15;
        int bn = bn0 + seq;
        int b = bn / NN, n = bn % NN;
        float v = x[((b*SS + s)*NN + n)*HH + c];
        sXr[idx] = v;
        sX[row*68 + c] = to_tf32(v);
    }
    __syncthreads();

    int w = t >> 5, lane = t & 31, g = lane >> 2, tg = lane & 3;

    // qkv = X @ Wi + bi : M=64, N=192, K=64. warp: mt=w>>2, 6 n-tiles
    {
        int mt = w >> 2, ng = w & 3;
        float4 d[6];
        #pragma unroll
        for (int i = 0; i < 6; i++) {
            int col = (ng*6 + i)*8 + 2*tg;
            d[i] = make_float4(sbi[col], sbi[col+1], sbi[col], sbi[col+1]);
        }
        #pragma unroll
        for (int kt = 0; kt < 8; kt++) {
            const float* Ab = sX + (mt*16)*68 + kt*8;
            float a0 = Ab[g*68 + tg],     a1 = Ab[(g+8)*68 + tg];
            float a2 = Ab[g*68 + tg + 4], a3 = Ab[(g+8)*68 + tg + 4];
            #pragma unroll
            for (int i = 0; i < 6; i++) {
                int nt = ng*6 + i;
                float2 b = *(const float2*)&sWif[((kt*24 + nt)*32 + lane)*2];
                mma_tf32(d[i], a0, a1, a2, a3, b.x, b.y);
            }
        }
        // store to sqkvT[(mt*192 + col)*20 + s]
        #pragma unroll
        for (int i = 0; i < 6; i++) {
            int col = (ng*6 + i)*8 + 2*tg;
            float* base = sqkvT + (mt*192 + col)*20;
            base[g]        = d[i].x;
            base[20 + g]   = d[i].y;
            base[g + 8]    = d[i].z;
            base[20 + g+8] = d[i].w;
        }
    }
    __syncthreads();

    // attention core (exact fp32): thread = (seq, head, q), 256 active
    if (t < 256) {
        int seq = t >> 6, h = (t >> 4) & 3, q = t & 15;
        const float* Qb = sqkvT + (seq*192 + h*16)*20;
        const float* Kb = Qb + 64*20;
        const float* Vb = Qb + 128*20;
        float sc[16];
        #pragma unroll
        for (int k = 0; k < 16; k++) sc[k] = 0.f;
        #pragma unroll
        for (int d = 0; d < 16; d++) {
            float qv = Qb[d*20 + q];
            const float4* kk = (const float4*)(Kb + d*20);
            float4 k0 = kk[0], k1 = kk[1], k2 = kk[2], k3 = kk[3];
            sc[0]+=qv*k0.x; sc[1]+=qv*k0.y; sc[2]+=qv*k0.z; sc[3]+=qv*k0.w;
            sc[4]+=qv*k1.x; sc[5]+=qv*k1.y; sc[6]+=qv*k1.z; sc[7]+=qv*k1.w;
            sc[8]+=qv*k2.x; sc[9]+=qv*k2.y; sc[10]+=qv*k2.z; sc[11]+=qv*k2.w;
            sc[12]+=qv*k3.x; sc[13]+=qv*k3.y; sc[14]+=qv*k3.z; sc[15]+=qv*k3.w;
        }
        float mx = -1e30f;
        #pragma unroll
        for (int k = 0; k < 16; k++) { sc[k] *= 0.25f; mx = fmaxf(mx, sc[k]); }
        float den = 0.f;
        #pragma unroll
        for (int k = 0; k < 16; k++) { sc[k] = expf(sc[k] - mx); den += sc[k]; }
        float inv = 1.f / den;
        #pragma unroll
        for (int d = 0; d < 16; d++) {
            const float4* vv = (const float4*)(Vb + d*20);
            float4 v0 = vv[0], v1 = vv[1], v2 = vv[2], v3 = vv[3];
            float o = sc[0]*v0.x + sc[1]*v0.y + sc[2]*v0.z + sc[3]*v0.w
                    + sc[4]*v1.x + sc[5]*v1.y + sc[6]*v1.z + sc[7]*v1.w
                    + sc[8]*v2.x + sc[9]*v2.y + sc[10]*v2.z + sc[11]*v2.w
                    + sc[12]*v3.x + sc[13]*v3.y + sc[14]*v3.z + sc[15]*v3.w;
            saoT[(seq*64 + h*16 + d)*20 + q] = to_tf32(o * inv);
        }
    }
    __syncthreads();

    // out-proj: Y = X + AO @ Wo + bo : M=64, N=64, K=64
    {
        int mt = w >> 2, np = w & 3;
        float4 d[2];
        #pragma unroll
        for (int i = 0; i < 2; i++) {
            int col = (np*2 + i)*8 + 2*tg;
            d[i] = make_float4(sbo[col], sbo[col+1], sbo[col], sbo[col+1]);
        }
        #pragma unroll
        for (int kt = 0; kt < 8; kt++) {
            // A[row][k] = saoT[(seq*64 + k)*20 + q], seq = mt
            const float* Ab = saoT + (mt*64 + kt*8)*20;
            float a0 = Ab[tg*20 + g],       a1 = Ab[tg*20 + g + 8];
            float a2 = Ab[(tg+4)*20 + g],   a3 = Ab[(tg+4)*20 + g + 8];
            #pragma unroll
            for (int i = 0; i < 2; i++) {
                int nt = np*2 + i;
                float2 b = *(const float2*)&sWof[((((kt<<3) + nt)<<5) + lane)*2];
                mma_tf32(d[i], a0, a1, a2, a3, b.x, b.y);
            }
        }
        int r0 = mt*16 + g;
        #pragma unroll
        for (int i = 0; i < 2; i++) {
            int col = (np*2 + i)*8 + 2*tg;
            sY[r0*64 + col]       = sXr[r0*64 + col]       + d[i].x;
            sY[r0*64 + col+1]     = sXr[r0*64 + col+1]     + d[i].y;
            sY[(r0+8)*64 + col]   = sXr[(r0+8)*64 + col]   + d[i].z;
            sY[(r0+8)*64 + col+1] = sXr[(r0+8)*64 + col+1] + d[i].w;
        }
    }
    __syncthreads();

    // LN: 64 rows, 8 lanes per row
    {
        int r = t >> 3, l = t & 7;
        float4 v1 = *(const float4*)&sY[r*64 + l*8];
        float4 v2 = *(const float4*)&sY[r*64 + l*8 + 4];
        float s  = v1.x+v1.y+v1.z+v1.w + v2.x+v2.y+v2.z+v2.w;
        float ss = v1.x*v1.x+v1.y*v1.y+v1.z*v1.z+v1.w*v1.w
                 + v2.x*v2.x+v2.y*v2.y+v2.z*v2.z+v2.w*v2.w;
        #pragma unroll
        for (int o = 1; o < 8; o <<= 1) {
            s  += __shfl_xor_sync(0xffffffffu, s,  o, 8);
            ss += __shfl_xor_sync(0xffffffffu, ss, o, 8);
        }
        if (l == 0) {
            float m = s * (1.f/64.f);
            float var = ss * (1.f/64.f) - m*m;
            smean[r] = m; sinv[r] = rsqrtf(var + 1e-5f);
        }
    }
    __syncthreads();
    for (int idx = t; idx < 4096; idx += 512) {
        int row = idx >> 6, c = idx & 63;
        int seq = row >> 4, s = row & 15;
        int bn = bn0 + seq;
        int b = bn / NN, n = bn % NN;
        g_x1[((b*SS + s)*NN + n)*HH + c] =
            (sY[idx] - smean[row]) * sinv[row] * stg[c] + stb[c];
    }
}

// ---------------- K2: edge embedding -> R ---------------------
__global__ void edge_emb_kernel(const float* __restrict__ ea,
                                const float* __restrict__ ew1, const float* __restrict__ eb1,
                                const float* __restrict__ ew2, const float* __restrict__ eb2,
                                const float* __restrict__ mw1, const float* __restrict__ mb1)
{
    extern __shared__ float sm[];
    float* sEw2 = sm;            // 64*64
    float* sWc  = sEw2 + 4096;   // 64*128
    float* sew1 = sWc + 8192;
    float* seb1 = sew1 + 64;
    float* seb2 = seb1 + 64;
    float* smb1 = seb2 + 64;     // 128
    float* semb = smb1 + 128;    // 64
    float* semb2= semb + 64;     // 64

    int t = threadIdx.x;   // 128
    for (int i = t; i < 4096; i += 128) sEw2[i] = ew2[i];
    for (int i = t; i < 8192; i += 128) sWc[i]  = mw1[128*128 + i];
    if (t < 64) { sew1[t] = ew1[t]; seb1[t] = eb1[t]; seb2[t] = eb2[t]; }
    smb1[t] = mb1[t];
    __syncthreads();

    for (int e = blockIdx.x; e < EE; e += gridDim.x) {
        if (t < 64) semb[t] = gelu_f(ea[e] * sew1[t] + seb1[t]);
        __syncthreads();
        if (t < 64) {
            float a = seb2[t];
            #pragma unroll 8
            for (int i = 0; i < 64; i++) a += semb[i] * sEw2[i*64 + t];
            semb2[t] = a;
        }
        __syncthreads();
        {
            float a = smb1[t];
            #pragma unroll 8
            for (int i = 0; i < 64; i++) a += semb2[i] * sWc[i*128 + t];
            g_R[e*128 + t] = a;
        }
        __syncthreads();
    }
}

// ---------------- K3: P,Q node GEMM via tf32 MMA ----------------
__global__ __launch_bounds__(512, 1) void pq_kernel(const float* __restrict__ mw1)
{
    extern __shared__ float sm[];
    float* sWf = sm;           // 64x256 in B-fragment order (KT=8, NT=32)
    float* sA  = sm + 16384;   // 32 x 68 (tf32)

    int t = threadIdx.x;
    for (int idx = t; idx < 16384; idx += 512) {
        int k = idx >> 8, c = idx & 255;
        float w = (c < 128) ? (mw1[k*128 + c] - mw1[(64+k)*128 + c])
                            :  mw1[(64+k)*128 + (c-128)];
        int kt = k >> 3, kk = k & 7, j = kk >> 2, tg = kk & 3;
        int nt = c >> 3, gg = c & 7;
        sWf[((((kt<<5) + nt)<<5) + (gg<<2) + tg)*2 + j] = to_tf32(w);
    }
    int rbase = blockIdx.x * 32;
    for (int idx = t; idx < 2048; idx += 512) {
        int r = idx >> 6, c = idx & 63;
        sA[r*68 + c] = to_tf32(g_x1[(rbase + r)*64 + c]);
    }
    __syncthreads();

    int w = t >> 5, lane = t & 31, g = lane >> 2, tg = lane & 3;
    int mt = w >> 3, ng = w & 7;
    float4 d[4];
    #pragma unroll
    for (int i = 0; i < 4; i++) d[i] = make_float4(0.f, 0.f, 0.f, 0.f);

    #pragma unroll
    for (int kt = 0; kt < 8; kt++) {
        const float* Ab = sA + (mt*16)*68 + kt*8;
        float a0 = Ab[g*68 + tg],     a1 = Ab[(g+8)*68 + tg];
        float a2 = Ab[g*68 + tg + 4], a3 = Ab[(g+8)*68 + tg + 4];
        #pragma unroll
        for (int i = 0; i < 4; i++) {
            int nt = ng*4 + i;
            float2 b = *(const float2*)&sWf[((((kt<<5) + nt)<<5) + lane)*2];
            mma_tf32(d[i], a0, a1, a2, a3, b.x, b.y);
        }
    }

    #pragma unroll
    for (int i = 0; i < 4; i++) {
        int nt = ng*4 + i;
        int col = nt*8 + 2*tg;
        float* base = (col < 128) ? (g_P + rbase*128 + col)
                                  : (g_Q + rbase*128 + (col - 128));
        int r0 = mt*16 + g;
        *(float2*)&base[r0*128]     = make_float2(d[i].x, d[i].y);
        *(float2*)&base[(r0+8)*128] = make_float2(d[i].z, d[i].w);
    }
}

// ---------------- K4: CSR gather aggregation (no atomics) -------------------
__global__ __launch_bounds__(256) void aggr_kernel()
{
    int w = (blockIdx.x * 256 + threadIdx.x) >> 5;   // 0..159999
    int lane = threadIdx.x & 31;
    int b = w & 31, dst = w >> 5;
    int row = b * NN + dst;
    float4 q = ((const float4*)g_Q)[row*32 + lane];
    float4 acc = make_float4(0.f, 0.f, 0.f, 0.f);
    int s = g_off[dst], e = g_off[dst+1];
    for (int k = s; k < e; k++) {
        int2 pe = g_epk[k];
        float4 p = ((const float4*)g_P)[(b*NN + pe.x)*32 + lane];
        float4 r = ((const float4*)g_R)[pe.y*32 + lane];
        acc.x += gelu_f(p.x + q.x + r.x);
        acc.y += gelu_f(p.y + q.y + r.y);
        acc.z += gelu_f(p.z + q.z + r.z);
        acc.w += gelu_f(p.w + q.w + r.w);
    }
    ((float4*)g_G)[row*32 + lane] = acc;
}

// ---------------- K5: update MLP via tf32 MMA + residual + LN ----------------
__global__ __launch_bounds__(512, 1) void update_kernel(
    const float* __restrict__ mw2, const float* __restrict__ mb2,
    const float* __restrict__ uw1, const float* __restrict__ ub1,
    const float* __restrict__ uw2, const float* __restrict__ ub2,
    const float* __restrict__ sg,  const float* __restrict__ sb)
{
    extern __shared__ float sm[];
    float* sW2f = sm;               // mw2 128x64 frag (KT=16,NT=8): 8192
    float* sU1f = sW2f + 8192;      // uw1 128x64 frag: 8192
    float* sU2f = sU1f + 8192;      // uw2 64x64 frag (KT=8,NT=8): 4096
    float* sG   = sU2f + 4096;      // 32 x 132 tf32
    float* sUin = sG + 4224;        // 32 x 132 tf32
    float* sHid = sUin + 4224;      // 32 x 68 tf32
    float* sXr  = sHid + 2176;      // 32 x 64 fp32
    float* sY   = sXr + 2048;       // 32 x 64
    float* smb2 = sY + 2048;        // 64
    float* sub1 = smb2 + 64;
    float* sub2 = sub1 + 64;
    float* ssg  = sub2 + 64;
    float* ssb  = ssg + 64;
    float* sdeg = ssb + 64;         // 32
    float* smean= sdeg + 32;        // 32
    float* sinv = smean + 32;       // 32

    int t = threadIdx.x;
    for (int idx = t; idx < 8192; idx += 512) {
        int k = idx >> 6, c = idx & 63;
        int kt = k >> 3, kk = k & 7, j = kk >> 2, tg = kk & 3;
        int nt = c >> 3, gg = c & 7;
        int fi = ((((kt<<3) + nt)<<5) + (gg<<2) + tg)*2 + j;
        sW2f[fi] = to_tf32(mw2[idx]);
        sU1f[fi] = to_tf32(uw1[idx]);
    }
    for (int idx = t; idx < 4096; idx += 512) {
        int k = idx >> 6, c = idx & 63;
        int kt = k >> 3, kk = k & 7, j = kk >> 2, tg = kk & 3;
        int nt = c >> 3, gg = c & 7;
        sU2f[((((kt<<3) + nt)<<5) + (gg<<2) + tg)*2 + j] = to_tf32(uw2[idx]);
    }
    if (t < 64) { smb2[t] = mb2[t]; sub1[t] = ub1[t]; sub2[t] = ub2[t]; ssg[t] = sg[t]; ssb[t] = sb[t]; }

    int rbase = blockIdx.x * 32;
    for (int idx = t; idx < 4096; idx += 512) {
        int c = idx & 127, r = idx >> 7;
        sG[r*132 + c] = to_tf32(g_G[(rbase + r)*128 + c]);
    }
    for (int idx = t; idx < 2048; idx += 512) {
        int c = idx & 63, r = idx >> 6;
        float v = g_x1[(rbase + r)*64 + c];
        sXr[r*64 + c] = v;
        sUin[r*132 + c] = to_tf32(v);
    }
    if (t < 32) {
        int n = (rbase + t) % NN;
        sdeg[t] = (float)(g_off[n+1] - g_off[n]);
    }
    __syncthreads();

    int w = t >> 5, lane = t & 31, g = lane >> 2, tg = lane & 3;
    int mt = w >> 3, nt = w & 7;
    int col = nt*8 + 2*tg;
    int r0 = mt*16 + g;

    // Stage0: aggr = G @ mw2 + deg*mb2
    {
        float4 d = make_float4(sdeg[r0]*smb2[col],   sdeg[r0]*smb2[col+1],
                               sdeg[r0+8]*smb2[col], sdeg[r0+8]*smb2[col+1]);
        #pragma unroll
        for (int kt = 0; kt < 16; kt++) {
            const float* Ab = sG + (mt*16)*132 + kt*8;
            float a0 = Ab[g*132 + tg],     a1 = Ab[(g+8)*132 + tg];
            float a2 = Ab[g*132 + tg + 4], a3 = Ab[(g+8)*132 + tg + 4];
            float2 b = *(const float2*)&sW2f[((((kt<<3) + nt)<<5) + lane)*2];
            mma_tf32(d, a0, a1, a2, a3, b.x, b.y);
        }
        *(float2*)&sUin[r0*132 + 64 + col]     = make_float2(to_tf32(d.x), to_tf32(d.y));
        *(float2*)&sUin[(r0+8)*132 + 64 + col] = make_float2(to_tf32(d.z), to_tf32(d.w));
    }
    __syncthreads();

    // Stage1: hid = gelu(Uin @ uw1 + ub1)
    {
        float4 d = make_float4(sub1[col], sub1[col+1], sub1[col], sub1[col+1]);
        #pragma unroll
        for (int kt = 0; kt < 16; kt++) {
            const float* Ab = sUin + (mt*16)*132 + kt*8;
            float a0 = Ab[g*132 + tg],     a1 = Ab[(g+8)*132 + tg];
            float a2 = Ab[g*132 + tg + 4], a3 = Ab[(g+8)*132 + tg + 4];
            float2 b = *(const float2*)&sU1f[((((kt<<3) + nt)<<5) + lane)*2];
            mma_tf32(d, a0, a1, a2, a3, b.x, b.y);
        }
        *(float2*)&sHid[r0*68 + col]     = make_float2(to_tf32(gelu_f(d.x)), to_tf32(gelu_f(d.y)));
        *(float2*)&sHid[(r0+8)*68 + col] = make_float2(to_tf32(gelu_f(d.z)), to_tf32(gelu_f(d.w)));
    }
    __syncthreads();

    // Stage2: y = xs + hid @ uw2 + ub2
    {
        float4 d = make_float4(sub2[col], sub2[col+1], sub2[col], sub2[col+1]);
        #pragma unroll
        for (int kt = 0; kt < 8; kt++) {
            const float* Ab = sHid + (mt*16)*68 + kt*8;
            float a0 = Ab[g*68 + tg],     a1 = Ab[(g+8)*68 + tg];
            float a2 = Ab[g*68 + tg + 4], a3 = Ab[(g+8)*68 + tg + 4];
            float2 b = *(const float2*)&sU2f[((((kt<<3) + nt)<<5) + lane)*2];
            mma_tf32(d, a0, a1, a2, a3, b.x, b.y);
        }
        sY[r0*64 + col]       = sXr[r0*64 + col]       + d.x;
        sY[r0*64 + col+1]     = sXr[r0*64 + col+1]     + d.y;
        sY[(r0+8)*64 + col]   = sXr[(r0+8)*64 + col]   + d.z;
        sY[(r0+8)*64 + col+1] = sXr[(r0+8)*64 + col+1] + d.w;
    }
    __syncthreads();

    // LN
    {
        int r = t >> 4, l = t & 15;
        float4 v = *(const float4*)&sY[r*64 + l*4];
        float s  = v.x + v.y + v.z + v.w;
        float ss = v.x*v.x + v.y*v.y + v.z*v.z + v.w*v.w;
        #pragma unroll
        for (int o = 1; o < 16; o <<= 1) {
            s  += __shfl_xor_sync(0xffffffffu, s,  o, 16);
            ss += __shfl_xor_sync(0xffffffffu, ss, o, 16);
        }
        if (l == 0) {
            float m = s * (1.f/64.f);
            float var = ss * (1.f/64.f) - m*m;
            smean[r] = m; sinv[r] = rsqrtf(var + 1e-5f);
        }
    }
    __syncthreads();
    for (int i = t; i < 2048; i += 512) {
        int r = i >> 6, cc = i & 63;
        g_x2[(rbase + r)*64 + cc] = (sY[i] - smean[r]) * sinv[r] * ssg[cc] + ssb[cc];
    }
}

// ---------------- K6: FFN via tf32 MMA + residual + LN -> d_out --------------
__global__ __launch_bounds__(512, 1) void ffn_kernel(
    const float* __restrict__ fw1, const float* __restrict__ fb1,
    const float* __restrict__ fw2, const float* __restrict__ fb2,
    const float* __restrict__ fg,  const float* __restrict__ fb,
    float* __restrict__ out)
{
    extern __shared__ float sm[];
    float* sW1f = sm;               // fw1 64x256 frag (KT=8,NT=32): 16384
    float* sW2f = sW1f + 16384;     // fw2 256x64 frag (KT=32,NT=8): 16384
    float* sA   = sW2f + 16384;     // X 32 x 68 tf32
    float* sH   = sA + 2176;        // H 32 x 260 tf32
    float* sXr  = sH + 8320;        // 32 x 64 fp32
    float* sY   = sXr + 2048;       // 32 x 64
    float* sb1  = sY + 2048;        // 256
    float* sb2  = sb1 + 256;        // 64
    float* sfg  = sb2 + 64;
    float* sfb  = sfg + 64;
    float* smean= sfb + 64;         // 32
    float* sinv = smean + 32;       // 32

    int t = threadIdx.x;
    for (int idx = t; idx < 16384; idx += 512) {
        int k = idx >> 8, c = idx & 255;
        int kt = k >> 3, kk = k & 7, j = kk >> 2, tg = kk & 3;
        int nt = c >> 3, gg = c & 7;
        sW1f[((((kt<<5) + nt)<<5) + (gg<<2) + tg)*2 + j] = to_tf32(fw1[idx]);
    }
    for (int idx = t; idx < 16384; idx += 512) {
        int k = idx >> 6, c = idx & 63;
        int kt = k >> 3, kk = k & 7, j = kk >> 2, tg = kk & 3;
        int nt = c >> 3, gg = c & 7;
        sW2f[((((kt<<3) + nt)<<5) + (gg<<2) + tg)*2 + j] = to_tf32(fw2[idx]);
    }
    if (t < 256) sb1[t] = fb1[t];
    if (t < 64) { sb2[t] = fb2[t]; sfg[t] = fg[t]; sfb[t] = fb[t]; }

    int rbase = blockIdx.x * 32;
    for (int idx = t; idx < 2048; idx += 512) {
        int c = idx & 63, r = idx >> 6;
        float v = g_x2[(rbase + r)*64 + c];
        sXr[r*64 + c] = v;
        sA[r*68 + c] = to_tf32(v);
    }
    __syncthreads();

    int w = t >> 5, lane = t & 31, g = lane >> 2, tg = lane & 3;

    // Stage1: H = gelu(X @ W1 + b1)
    {
        int mt = w >> 3, ng = w & 7;
        float4 d[4];
        #pragma unroll
        for (int i = 0; i < 4; i++) {
            int col = (ng*4 + i)*8 + 2*tg;
            d[i] = make_float4(sb1[col], sb1[col+1], sb1[col], sb1[col+1]);
        }
        #pragma unroll
        for (int kt = 0; kt < 8; kt++) {
            const float* Ab = sA + (mt*16)*68 + kt*8;
            float a0 = Ab[g*68 + tg],     a1 = Ab[(g+8)*68 + tg];
            float a2 = Ab[g*68 + tg + 4], a3 = Ab[(g+8)*68 + tg + 4];
            #pragma unroll
            for (int i = 0; i < 4; i++) {
                int nt = ng*4 + i;
                float2 b = *(const float2*)&sW1f[((((kt<<5) + nt)<<5) + lane)*2];
                mma_tf32(d[i], a0, a1, a2, a3, b.x, b.y);
            }
        }
        int r0 = mt*16 + g;
        #pragma unroll
        for (int i = 0; i < 4; i++) {
            int col = (ng*4 + i)*8 + 2*tg;
            *(float2*)&sH[r0*260 + col]     = make_float2(to_tf32(gelu_f(d[i].x)), to_tf32(gelu_f(d[i].y)));
            *(float2*)&sH[(r0+8)*260 + col] = make_float2(to_tf32(gelu_f(d[i].z)), to_tf32(gelu_f(d[i].w)));
        }
    }
    __syncthreads();

    // Stage2: Y = X + H @ W2 + b2
    {
        int mt = w >> 3, nt = w & 7;
        int col = nt*8 + 2*tg;
        int r0 = mt*16 + g;
        float4 d = make_float4(sb2[col], sb2[col+1], sb2[col], sb2[col+1]);
        #pragma unroll
        for (int kt = 0; kt < 32; kt++) {
            const float* Ab = sH + (mt*16)*260 + kt*8;
            float a0 = Ab[g*260 + tg],     a1 = Ab[(g+8)*260 + tg];
            float a2 = Ab[g*260 + tg + 4], a3 = Ab[(g+8)*260 + tg + 4];
            float2 b = *(const float2*)&sW2f[((((kt<<3) + nt)<<5) + lane)*2];
            mma_tf32(d, a0, a1, a2, a3, b.x, b.y);
        }
        sY[r0*64 + col]       = sXr[r0*64 + col]       + d.x;
        sY[r0*64 + col+1]     = sXr[r0*64 + col+1]     + d.y;
        sY[(r0+8)*64 + col]   = sXr[(r0+8)*64 + col]   + d.z;
        sY[(r0+8)*64 + col+1] = sXr[(r0+8)*64 + col+1] + d.w;
    }
    __syncthreads();

    // LN
    {
        int r = t >> 4, l = t & 15;
        float4 v = *(const float4*)&sY[r*64 + l*4];
        float s  = v.x + v.y + v.z + v.w;
        float ss = v.x*v.x + v.y*v.y + v.z*v.z + v.w*v.w;
        #pragma unroll
        for (int o = 1; o < 16; o <<= 1) {
            s  += __shfl_xor_sync(0xffffffffu, s,  o, 16);
            ss += __shfl_xor_sync(0xffffffffu, ss, o, 16);
        }
        if (l == 0) {
            float m = s * (1.f/64.f);
            float var = ss * (1.f/64.f) - m*m;
            smean[r] = m; sinv[r] = rsqrtf(var + 1e-5f);
        }
    }
    __syncthreads();
    for (int i = t; i < 2048; i += 512) {
        int r = i >> 6, cc = i & 63;
        out[(rbase + r)*64 + cc] = (sY[i] - smean[r]) * sinv[r] * sfg[cc] + sfb[cc];
    }
}

// ---------------- host launcher ---------------------------------------------
extern "C" void kernel_launch(void* const* d_in, const int* in_sizes, int n_in,
                              void* d_out, int out_size)
{
    (void)in_sizes; (void)n_in; (void)out_size;
    const float* x    = (const float*)d_in[0];
    const int*   ei   = (const int*)  d_in[1];
    const float* ea   = (const float*)d_in[2];
    const float* ipw  = (const float*)d_in[3];
    const float* ipb  = (const float*)d_in[4];
    const float* opw  = (const float*)d_in[5];
    const float* opb  = (const float*)d_in[6];
    const float* tng  = (const float*)d_in[7];
    const float* tnb  = (const float*)d_in[8];
    const float* ew1  = (const float*)d_in[9];
    const float* eb1  = (const float*)d_in[10];
    const float* ew2  = (const float*)d_in[11];
    const float* eb2  = (const float*)d_in[12];
    const float* mw1  = (const float*)d_in[13];
    const float* mb1  = (const float*)d_in[14];
    const float* mw2  = (const float*)d_in[15];
    const float* mb2  = (const float*)d_in[16];
    const float* uw1  = (const float*)d_in[17];
    const float* ub1  = (const float*)d_in[18];
    const float* uw2  = (const float*)d_in[19];
    const float* ub2  = (const float*)d_in[20];
    const float* sng  = (const float*)d_in[21];
    const float* snb  = (const float*)d_in[22];
    const float* fw1  = (const float*)d_in[23];
    const float* fb1  = (const float*)d_in[24];
    const float* fw2  = (const float*)d_in[25];
    const float* fb2  = (const float*)d_in[26];
    const float* fng  = (const float*)d_in[27];
    const float* fnb  = (const float*)d_in[28];
    float* out = (float*)d_out;

    const int SM_ATT = 49920 * 4;   // 199680
    const int SM_EE  = 12736 * 4;
    const int SM_PQ  = (16384 + 2176) * 4;
    const int SM_UPD = (8192+8192+4096+4224+4224+2176+2048+2048+64*5+32*3) * 4;
    const int SM_FFN = (16384+16384+2176+8320+2048+2048+256+64*3+32*2) * 4;
    cudaFuncSetAttribute(attn_kernel,     cudaFuncAttributeMaxDynamicSharedMemorySize, SM_ATT);
    cudaFuncSetAttribute(edge_emb_kernel, cudaFuncAttributeMaxDynamicSharedMemorySize, SM_EE);
    cudaFuncSetAttribute(pq_kernel,       cudaFuncAttributeMaxDynamicSharedMemorySize, SM_PQ);
    cudaFuncSetAttribute(update_kernel,   cudaFuncAttributeMaxDynamicSharedMemorySize, SM_UPD);
    cudaFuncSetAttribute(ffn_kernel,      cudaFuncAttributeMaxDynamicSharedMemorySize, SM_FFN);

    csr_zero_kernel  <<<20, 256>>>();
    attn_kernel      <<<2500, 512, SM_ATT>>>(x, ipw, ipb, opw, opb, tng, tnb);
    csr_count_kernel <<<79, 256>>>(ei);
    csr_scan_kernel  <<<1, 1024>>>();
    csr_fill_kernel  <<<79, 256>>>(ei);
    edge_emb_kernel  <<<256, 128, SM_EE>>>(ea, ew1, eb1, ew2, eb2, mw1, mb1);
    pq_kernel        <<<5000, 512, SM_PQ>>>(mw1);
    aggr_kernel      <<<20000, 256>>>();
    update_kernel    <<<5000, 512, SM_UPD>>>(mw2, mb2, uw1, ub1, uw2, ub2, sng, snb);
    ffn_kernel       <<<5000, 512, SM_FFN>>>(fw1, fb1, fw2, fb2, fng, fnb, out);
}

// round 6
// speedup vs baseline: 3.7978x; 1.9209x over previous
#include <cuda_runtime.h>

// ---------------- problem constants ----------------
#define BB    2
#define SS    16
#define NN    5000
#define HH    64
#define EE    20000
#define BSS   (BB*SS)      // 32
#define BNN   (BB*NN)      // 10000
#define NROWS (BSS*NN)     // 160000

// ---------------- scratch (device globals) ----------------
__device__ __align__(16) float g_x1[NROWS*HH];
__device__ __align__(16) float g_x2[NROWS*HH];
__device__ __align__(16) float g_P [NROWS*128];
__device__ __align__(16) float g_Q [NROWS*128];
__device__ __align__(16) float g_R [EE*128];
__device__ __align__(16) float g_G [NROWS*128];
__device__ int  g_cnt[NN];
__device__ int  g_cur[NN];
__device__ int  g_off[NN+1];
__device__ int2 g_epk[EE];     // (src, e) sorted by dst

// fragment-permuted weights (filled once per launch by prep_kernel)
__device__ __align__(16) float g_Wif [12288];   // in_proj 64x192, NT=24
__device__ __align__(16) float g_Wof [4096];    // out_proj 64x64, NT=8
__device__ __align__(16) float g_Wpqf[16384];   // [Wa-Wb | Wb] 64x256, NT=32
__device__ __align__(16) float g_W2f [8192];    // mw2 128x64, NT=8
__device__ __align__(16) float g_U1f [8192];    // uw1 128x64, NT=8
__device__ __align__(16) float g_U2f [4096];    // uw2 64x64, NT=8
__device__ __align__(16) float g_F1f [16384];   // fw1 64x256, NT=32
__device__ __align__(16) float g_F2f [16384];   // fw2 256x64, NT=8

__device__ __forceinline__ float gelu_f(float v) {
    return 0.5f * v * (1.0f + erff(v * 0.70710678118654752f));
}

__device__ __forceinline__ float to_tf32(float x) {
    unsigned r;
    asm("cvt.rna.tf32.f32 %0, %1;" : "=r"(r) : "f"(x));
    return __uint_as_float(r);
}

__device__ __forceinline__ int fragidx(int k, int c, int NT) {
    int kt = k >> 3, kk = k & 7, j = kk >> 2, tg = kk & 3;
    int nt = c >> 3, gg = c & 7;
    return ((kt*NT + nt)*32 + (gg<<2) + tg)*2 + j;
}

// mma.m16n8k8 tf32: D(16x8) += A(16x8,row) * B(8x8,col)
__device__ __forceinline__ void mma_tf32(float4& d,
    float a0, float a1, float a2, float a3, float b0, float b1)
{
    asm volatile(
      "mma.sync.aligned.m16n8k8.row.col.f32.tf32.tf32.f32 "
      "{%0,%1,%2,%3},{%4,%5,%6,%7},{%8,%9},{%0,%1,%2,%3};\n"
      : "+f"(d.x), "+f"(d.y), "+f"(d.z), "+f"(d.w)
      : "r"(__float_as_uint(a0)), "r"(__float_as_uint(a1)),
        "r"(__float_as_uint(a2)), "r"(__float_as_uint(a3)),
        "r"(__float_as_uint(b0)), "r"(__float_as_uint(b1)));
}

// ---------------- prep: permute weights to fragment order -------------------
__global__ void prep_kernel(
    const float* __restrict__ Wi,  const float* __restrict__ Wo,
    const float* __restrict__ mw1, const float* __restrict__ mw2,
    const float* __restrict__ uw1, const float* __restrict__ uw2,
    const float* __restrict__ fw1, const float* __restrict__ fw2)
{
    int i = blockIdx.x * 512 + threadIdx.x;   // grid 168*512 = 86016
    if (i < 12288) {                              // Wi 64x192
        int k = i / 192, c = i % 192;
        g_Wif[fragidx(k, c, 24)] = to_tf32(Wi[i]);
    } else if (i < 16384) {                       // Wo 64x64
        int idx = i - 12288, k = idx >> 6, c = idx & 63;
        g_Wof[fragidx(k, c, 8)] = to_tf32(Wo[idx]);
    } else if (i < 32768) {                       // pq combined 64x256
        int idx = i - 16384, k = idx >> 8, c = idx & 255;
        float w = (c < 128) ? (mw1[k*128 + c] - mw1[(64+k)*128 + c])
                            :  mw1[(64+k)*128 + (c-128)];
        g_Wpqf[fragidx(k, c, 32)] = to_tf32(w);
    } else if (i < 40960) {                       // mw2 128x64
        int idx = i - 32768, k = idx >> 6, c = idx & 63;
        g_W2f[fragidx(k, c, 8)] = to_tf32(mw2[idx]);
    } else if (i < 49152) {                       // uw1 128x64
        int idx = i - 40960, k = idx >> 6, c = idx & 63;
        g_U1f[fragidx(k, c, 8)] = to_tf32(uw1[idx]);
    } else if (i < 53248) {                       // uw2 64x64
        int idx = i - 49152, k = idx >> 6, c = idx & 63;
        g_U2f[fragidx(k, c, 8)] = to_tf32(uw2[idx]);
    } else if (i < 69632) {                       // fw1 64x256
        int idx = i - 53248, k = idx >> 8, c = idx & 255;
        g_F1f[fragidx(k, c, 32)] = to_tf32(fw1[idx]);
    } else if (i < 86016) {                       // fw2 256x64
        int idx = i - 69632, k = idx >> 6, c = idx & 63;
        g_F2f[fragidx(k, c, 8)] = to_tf32(fw2[idx]);
    }
}

// ---------------- CSR build ----------------
__global__ void csr_zero_kernel() {
    int i = blockIdx.x * blockDim.x + threadIdx.x;
    if (i < NN) g_cnt[i] = 0;
}
__global__ void csr_count_kernel(const int* __restrict__ ei) {
    int e = blockIdx.x * blockDim.x + threadIdx.x;
    if (e < EE) atomicAdd(&g_cnt[ei[EE + e]], 1);
}
__global__ void csr_scan_kernel() {
    __shared__ int sbuf[1024];
    __shared__ int scarry;
    int t = threadIdx.x;
    if (t == 0) scarry = 0;
    __syncthreads();
    for (int ch = 0; ch < 5; ch++) {
        int idx = ch * 1024 + t;
        int v = (idx < NN) ? g_cnt[idx] : 0;
        sbuf[t] = v; __syncthreads();
        for (int o = 1; o < 1024; o <<= 1) {
            int x = (t >= o) ? sbuf[t - o] : 0;
            __syncthreads();
            sbuf[t] += x;
            __syncthreads();
        }
        int incl = sbuf[t];
        int base = scarry;
        if (idx < NN) { int off = base + incl - v; g_off[idx] = off; g_cur[idx] = off; }
        __syncthreads();
        if (t == 1023) scarry = base + sbuf[1023];
        __syncthreads();
    }
    if (t == 0) g_off[NN] = scarry;
}
__global__ void csr_fill_kernel(const int* __restrict__ ei) {
    int e = blockIdx.x * blockDim.x + threadIdx.x;
    if (e < EE) {
        int dst = ei[EE + e];
        int pos = atomicAdd(&g_cur[dst], 1);
        g_epk[pos] = make_int2(ei[e], e);
    }
}

// ---------------- K1: temporal attention via tf32 MMA + residual + LN -------
// 512 thr, 4 (b,n) sequences per block (M=64). Weights from g_Wif/g_Wof (gmem).
__global__ __launch_bounds__(512, 2) void attn_kernel(
    const float* __restrict__ x,
    const float* __restrict__ bi, const float* __restrict__ bo,
    const float* __restrict__ tg_, const float* __restrict__ tb_)
{
    extern __shared__ float sm[];
    float* sbi  = sm;            // 192
    float* sbo  = sbi + 192;     // 64
    float* stg  = sbo + 64;      // 64
    float* stb  = stg + 64;      // 64
    float* sX   = stb + 64;      // 64x68 tf32 (also residual source)
    float* sqkvT= sX + 4352;     // [seq<4][j<192][s<16] pad20 = 15360
    float* saoT = sqkvT + 15360; // [seq<4][d<64][q<16] pad20 = 5120
    float* sY   = sqkvT;         // alias: sqkvT dead after softmax
    float* smean= saoT + 5120;   // 64
    float* sinv = smean + 64;    // 64

    int t = threadIdx.x;
    if (t < 192) sbi[t] = bi[t];
    if (t < 64) { sbo[t] = bo[t]; stg[t] = tg_[t]; stb[t] = tb_[t]; }

    int bn0 = blockIdx.x * 4;
    for (int idx = t; idx < 4096; idx += 512) {
        int row = idx >> 6, c = idx & 63;
        int seq = row >> 4, s = row & 15;
        int bn = bn0 + seq;
        int b = bn / NN, n = bn % NN;
        sX[row*68 + c] = to_tf32(x[((b*SS + s)*NN + n)*HH + c]);
    }
    __syncthreads();

    int w = t >> 5, lane = t & 31, g = lane >> 2, tg = lane & 3;

    // qkv = X @ Wi + bi : M=64, N=192, K=64. warp: mt=w>>2, 6 n-tiles
    {
        int mt = w >> 2, ng = w & 3;
        float4 d[6];
        #pragma unroll
        for (int i = 0; i < 6; i++) {
            int col = (ng*6 + i)*8 + 2*tg;
            d[i] = make_float4(sbi[col], sbi[col+1], sbi[col], sbi[col+1]);
        }
        #pragma unroll
        for (int kt = 0; kt < 8; kt++) {
            const float* Ab = sX + (mt*16)*68 + kt*8;
            float a0 = Ab[g*68 + tg],     a1 = Ab[(g+8)*68 + tg];
            float a2 = Ab[g*68 + tg + 4], a3 = Ab[(g+8)*68 + tg + 4];
            #pragma unroll
            for (int i = 0; i < 6; i++) {
                int nt = ng*6 + i;
                float2 b = __ldg((const float2*)&g_Wif[((kt*24 + nt)*32 + lane)*2]);
                mma_tf32(d[i], a0, a1, a2, a3, b.x, b.y);
            }
        }
        #pragma unroll
        for (int i = 0; i < 6; i++) {
            int col = (ng*6 + i)*8 + 2*tg;
            float* base = sqkvT + (mt*192 + col)*20;
            base[g]        = d[i].x;
            base[20 + g]   = d[i].y;
            base[g + 8]    = d[i].z;
            base[20 + g+8] = d[i].w;
        }
    }
    __syncthreads();

    // attention core (exact fp32): thread = (seq, head, q), 256 active
    if (t < 256) {
        int seq = t >> 6, h = (t >> 4) & 3, q = t & 15;
        const float* Qb = sqkvT + (seq*192 + h*16)*20;
        const float* Kb = Qb + 64*20;
        const float* Vb = Qb + 128*20;
        float sc[16];
        #pragma unroll
        for (int k = 0; k < 16; k++) sc[k] = 0.f;
        #pragma unroll
        for (int d = 0; d < 16; d++) {
            float qv = Qb[d*20 + q];
            const float4* kk = (const float4*)(Kb + d*20);
            float4 k0 = kk[0], k1 = kk[1], k2 = kk[2], k3 = kk[3];
            sc[0]+=qv*k0.x; sc[1]+=qv*k0.y; sc[2]+=qv*k0.z; sc[3]+=qv*k0.w;
            sc[4]+=qv*k1.x; sc[5]+=qv*k1.y; sc[6]+=qv*k1.z; sc[7]+=qv*k1.w;
            sc[8]+=qv*k2.x; sc[9]+=qv*k2.y; sc[10]+=qv*k2.z; sc[11]+=qv*k2.w;
            sc[12]+=qv*k3.x; sc[13]+=qv*k3.y; sc[14]+=qv*k3.z; sc[15]+=qv*k3.w;
        }
        float mx = -1e30f;
        #pragma unroll
        for (int k = 0; k < 16; k++) { sc[k] *= 0.25f; mx = fmaxf(mx, sc[k]); }
        float den = 0.f;
        #pragma unroll
        for (int k = 0; k < 16; k++) { sc[k] = expf(sc[k] - mx); den += sc[k]; }
        float inv = 1.f / den;
        #pragma unroll
        for (int d = 0; d < 16; d++) {
            const float4* vv = (const float4*)(Vb + d*20);
            float4 v0 = vv[0], v1 = vv[1], v2 = vv[2], v3 = vv[3];
            float o = sc[0]*v0.x + sc[1]*v0.y + sc[2]*v0.z + sc[3]*v0.w
                    + sc[4]*v1.x + sc[5]*v1.y + sc[6]*v1.z + sc[7]*v1.w
                    + sc[8]*v2.x + sc[9]*v2.y + sc[10]*v2.z + sc[11]*v2.w
                    + sc[12]*v3.x + sc[13]*v3.y + sc[14]*v3.z + sc[15]*v3.w;
            saoT[(seq*64 + h*16 + d)*20 + q] = to_tf32(o * inv);
        }
    }
    __syncthreads();

    // out-proj: Y = X + AO @ Wo + bo (sY aliases sqkvT; saoT still live)
    {
        int mt = w >> 2, np = w & 3;
        float4 d[2];
        #pragma unroll
        for (int i = 0; i < 2; i++) {
            int col = (np*2 + i)*8 + 2*tg;
            d[i] = make_float4(sbo[col], sbo[col+1], sbo[col], sbo[col+1]);
        }
        #pragma unroll
        for (int kt = 0; kt < 8; kt++) {
            const float* Ab = saoT + (mt*64 + kt*8)*20;
            float a0 = Ab[tg*20 + g],       a1 = Ab[tg*20 + g + 8];
            float a2 = Ab[(tg+4)*20 + g],   a3 = Ab[(tg+4)*20 + g + 8];
            #pragma unroll
            for (int i = 0; i < 2; i++) {
                int nt = np*2 + i;
                float2 b = __ldg((const float2*)&g_Wof[((((kt<<3) + nt)<<5) + lane)*2]);
                mma_tf32(d[i], a0, a1, a2, a3, b.x, b.y);
            }
        }
        int r0 = mt*16 + g;
        #pragma unroll
        for (int i = 0; i < 2; i++) {
            int col = (np*2 + i)*8 + 2*tg;
            sY[r0*64 + col]       = sX[r0*68 + col]       + d[i].x;
            sY[r0*64 + col+1]     = sX[r0*68 + col+1]     + d[i].y;
            sY[(r0+8)*64 + col]   = sX[(r0+8)*68 + col]   + d[i].z;
            sY[(r0+8)*64 + col+1] = sX[(r0+8)*68 + col+1] + d[i].w;
        }
    }
    __syncthreads();

    // LN: 64 rows, 8 lanes per row
    {
        int r = t >> 3, l = t & 7;
        float4 v1 = *(const float4*)&sY[r*64 + l*8];
        float4 v2 = *(const float4*)&sY[r*64 + l*8 + 4];
        float s  = v1.x+v1.y+v1.z+v1.w + v2.x+v2.y+v2.z+v2.w;
        float ss = v1.x*v1.x+v1.y*v1.y+v1.z*v1.z+v1.w*v1.w
                 + v2.x*v2.x+v2.y*v2.y+v2.z*v2.z+v2.w*v2.w;
        #pragma unroll
        for (int o = 1; o < 8; o <<= 1) {
            s  += __shfl_xor_sync(0xffffffffu, s,  o, 8);
            ss += __shfl_xor_sync(0xffffffffu, ss, o, 8);
        }
        if (l == 0) {
            float m = s * (1.f/64.f);
            float var = ss * (1.f/64.f) - m*m;
            smean[r] = m; sinv[r] = rsqrtf(var + 1e-5f);
        }
    }
    __syncthreads();
    for (int idx = t; idx < 4096; idx += 512) {
        int row = idx >> 6, c = idx & 63;
        int seq = row >> 4, s = row & 15;
        int bn = bn0 + seq;
        int b = bn / NN, n = bn % NN;
        g_x1[((b*SS + s)*NN + n)*HH + c] =
            (sY[idx] - smean[row]) * sinv[row] * stg[c] + stb[c];
    }
}

// ---------------- K2: edge embedding -> R ---------------------
__global__ void edge_emb_kernel(const float* __restrict__ ea,
                                const float* __restrict__ ew1, const float* __restrict__ eb1,
                                const float* __restrict__ ew2, const float* __restrict__ eb2,
                                const float* __restrict__ mw1, const float* __restrict__ mb1)
{
    extern __shared__ float sm[];
    float* sEw2 = sm;            // 64*64
    float* sWc  = sEw2 + 4096;   // 64*128
    float* sew1 = sWc + 8192;
    float* seb1 = sew1 + 64;
    float* seb2 = seb1 + 64;
    float* smb1 = seb2 + 64;     // 128
    float* semb = smb1 + 128;    // 64
    float* semb2= semb + 64;     // 64

    int t = threadIdx.x;   // 128
    for (int i = t; i < 4096; i += 128) sEw2[i] = ew2[i];
    for (int i = t; i < 8192; i += 128) sWc[i]  = mw1[128*128 + i];
    if (t < 64) { sew1[t] = ew1[t]; seb1[t] = eb1[t]; seb2[t] = eb2[t]; }
    smb1[t] = mb1[t];
    __syncthreads();

    for (int e = blockIdx.x; e < EE; e += gridDim.x) {
        if (t < 64) semb[t] = gelu_f(ea[e] * sew1[t] + seb1[t]);
        __syncthreads();
        if (t < 64) {
            float a = seb2[t];
            #pragma unroll 8
            for (int i = 0; i < 64; i++) a += semb[i] * sEw2[i*64 + t];
            semb2[t] = a;
        }
        __syncthreads();
        {
            float a = smb1[t];
            #pragma unroll 8
            for (int i = 0; i < 64; i++) a += semb2[i] * sWc[i*128 + t];
            g_R[e*128 + t] = a;
        }
        __syncthreads();
    }
}

// ---------------- K3: P,Q node GEMM via tf32 MMA (weights from gmem) --------
__global__ __launch_bounds__(512) void pq_kernel()
{
    extern __shared__ float sm[];
    float* sA = sm;   // 32 x 68 (tf32)

    int t = threadIdx.x;
    int rbase = blockIdx.x * 32;
    for (int idx = t; idx < 2048; idx += 512) {
        int r = idx >> 6, c = idx & 63;
        sA[r*68 + c] = to_tf32(g_x1[(rbase + r)*64 + c]);
    }
    __syncthreads();

    int w = t >> 5, lane = t & 31, g = lane >> 2, tg = lane & 3;
    int mt = w >> 3, ng = w & 7;
    float4 d[4];
    #pragma unroll
    for (int i = 0; i < 4; i++) d[i] = make_float4(0.f, 0.f, 0.f, 0.f);

    #pragma unroll
    for (int kt = 0; kt < 8; kt++) {
        const float* Ab = sA + (mt*16)*68 + kt*8;
        float a0 = Ab[g*68 + tg],     a1 = Ab[(g+8)*68 + tg];
        float a2 = Ab[g*68 + tg + 4], a3 = Ab[(g+8)*68 + tg + 4];
        #pragma unroll
        for (int i = 0; i < 4; i++) {
            int nt = ng*4 + i;
            float2 b = __ldg((const float2*)&g_Wpqf[((((kt<<5) + nt)<<5) + lane)*2]);
            mma_tf32(d[i], a0, a1, a2, a3, b.x, b.y);
        }
    }

    #pragma unroll
    for (int i = 0; i < 4; i++) {
        int nt = ng*4 + i;
        int col = nt*8 + 2*tg;
        float* base = (col < 128) ? (g_P + rbase*128 + col)
                                  : (g_Q + rbase*128 + (col - 128));
        int r0 = mt*16 + g;
        *(float2*)&base[r0*128]     = make_float2(d[i].x, d[i].y);
        *(float2*)&base[(r0+8)*128] = make_float2(d[i].z, d[i].w);
    }
}

// ---------------- K4: CSR gather aggregation (pipelined, no atomics) --------
__global__ __launch_bounds__(256) void aggr_kernel()
{
    int w = (blockIdx.x * 256 + threadIdx.x) >> 5;   // 0..159999
    int lane = threadIdx.x & 31;
    int b = w & 31, dst = w >> 5;
    int row = b * NN + dst;
    float4 q = __ldg(((const float4*)g_Q) + row*32 + lane);
    float4 acc = make_float4(0.f, 0.f, 0.f, 0.f);
    int s = __ldg(&g_off[dst]), e = __ldg(&g_off[dst+1]);
    if (s < e) {
        int2 pe = __ldg(&g_epk[s]);
        float4 p = __ldg(((const float4*)g_P) + (b*NN + pe.x)*32 + lane);
        float4 r = __ldg(((const float4*)g_R) + pe.y*32 + lane);
        for (int k = s + 1; k < e; k++) {
            int2 pe2 = __ldg(&g_epk[k]);
            float4 p2 = __ldg(((const float4*)g_P) + (b*NN + pe2.x)*32 + lane);
            float4 r2 = __ldg(((const float4*)g_R) + pe2.y*32 + lane);
            acc.x += gelu_f(p.x + q.x + r.x);
            acc.y += gelu_f(p.y + q.y + r.y);
            acc.z += gelu_f(p.z + q.z + r.z);
            acc.w += gelu_f(p.w + q.w + r.w);
            p = p2; r = r2;
        }
        acc.x += gelu_f(p.x + q.x + r.x);
        acc.y += gelu_f(p.y + q.y + r.y);
        acc.z += gelu_f(p.z + q.z + r.z);
        acc.w += gelu_f(p.w + q.w + r.w);
    }
    ((float4*)g_G)[row*32 + lane] = acc;
}

// ---------------- K5: update MLP via tf32 MMA + residual + LN ----------------
__global__ __launch_bounds__(512) void update_kernel(
    const float* __restrict__ mb2, const float* __restrict__ ub1,
    const float* __restrict__ ub2,
    const float* __restrict__ sg,  const float* __restrict__ sb)
{
    extern __shared__ float sm[];
    float* sG   = sm;               // 32 x 132 tf32
    float* sUin = sG + 4224;        // 32 x 132 tf32
    float* sHid = sUin + 4224;      // 32 x 68 tf32
    float* sXr  = sHid + 2176;      // 32 x 64 fp32
    float* sY   = sXr + 2048;       // 32 x 64
    float* smb2 = sY + 2048;        // 64
    float* sub1 = smb2 + 64;
    float* sub2 = sub1 + 64;
    float* ssg  = sub2 + 64;
    float* ssb  = ssg + 64;
    float* sdeg = ssb + 64;         // 32
    float* smean= sdeg + 32;        // 32
    float* sinv = smean + 32;       // 32

    int t = threadIdx.x;
    if (t < 64) { smb2[t] = mb2[t]; sub1[t] = ub1[t]; sub2[t] = ub2[t]; ssg[t] = sg[t]; ssb[t] = sb[t]; }

    int rbase = blockIdx.x * 32;
    for (int idx = t; idx < 4096; idx += 512) {
        int c = idx & 127, r = idx >> 7;
        sG[r*132 + c] = to_tf32(g_G[(rbase + r)*128 + c]);
    }
    for (int idx = t; idx < 2048; idx += 512) {
        int c = idx & 63, r = idx >> 6;
        float v = g_x1[(rbase + r)*64 + c];
        sXr[r*64 + c] = v;
        sUin[r*132 + c] = to_tf32(v);
    }
    if (t < 32) {
        int n = (rbase + t) % NN;
        sdeg[t] = (float)(g_off[n+1] - g_off[n]);
    }
    __syncthreads();

    int w = t >> 5, lane = t & 31, g = lane >> 2, tg = lane & 3;
    int mt = w >> 3, nt = w & 7;
    int col = nt*8 + 2*tg;
    int r0 = mt*16 + g;

    // Stage0: aggr = G @ mw2 + deg*mb2
    {
        float4 d = make_float4(sdeg[r0]*smb2[col],   sdeg[r0]*smb2[col+1],
                               sdeg[r0+8]*smb2[col], sdeg[r0+8]*smb2[col+1]);
        #pragma unroll
        for (int kt = 0; kt < 16; kt++) {
            const float* Ab = sG + (mt*16)*132 + kt*8;
            float a0 = Ab[g*132 + tg],     a1 = Ab[(g+8)*132 + tg];
            float a2 = Ab[g*132 + tg + 4], a3 = Ab[(g+8)*132 + tg + 4];
            float2 b = __ldg((const float2*)&g_W2f[((((kt<<3) + nt)<<5) + lane)*2]);
            mma_tf32(d, a0, a1, a2, a3, b.x, b.y);
        }
        *(float2*)&sUin[r0*132 + 64 + col]     = make_float2(to_tf32(d.x), to_tf32(d.y));
        *(float2*)&sUin[(r0+8)*132 + 64 + col] = make_float2(to_tf32(d.z), to_tf32(d.w));
    }
    __syncthreads();

    // Stage1: hid = gelu(Uin @ uw1 + ub1)
    {
        float4 d = make_float4(sub1[col], sub1[col+1], sub1[col], sub1[col+1]);
        #pragma unroll
        for (int kt = 0; kt < 16; kt++) {
            const float* Ab = sUin + (mt*16)*132 + kt*8;
            float a0 = Ab[g*132 + tg],     a1 = Ab[(g+8)*132 + tg];
            float a2 = Ab[g*132 + tg + 4], a3 = Ab[(g+8)*132 + tg + 4];
            float2 b = __ldg((const float2*)&g_U1f[((((kt<<3) + nt)<<5) + lane)*2]);
            mma_tf32(d, a0, a1, a2, a3, b.x, b.y);
        }
        *(float2*)&sHid[r0*68 + col]     = make_float2(to_tf32(gelu_f(d.x)), to_tf32(gelu_f(d.y)));
        *(float2*)&sHid[(r0+8)*68 + col] = make_float2(to_tf32(gelu_f(d.z)), to_tf32(gelu_f(d.w)));
    }
    __syncthreads();

    // Stage2: y = xs + hid @ uw2 + ub2
    {
        float4 d = make_float4(sub2[col], sub2[col+1], sub2[col], sub2[col+1]);
        #pragma unroll
        for (int kt = 0; kt < 8; kt++) {
            const float* Ab = sHid + (mt*16)*68 + kt*8;
            float a0 = Ab[g*68 + tg],     a1 = Ab[(g+8)*68 + tg];
            float a2 = Ab[g*68 + tg + 4], a3 = Ab[(g+8)*68 + tg + 4];
            float2 b = __ldg((const float2*)&g_U2f[((((kt<<3) + nt)<<5) + lane)*2]);
            mma_tf32(d, a0, a1, a2, a3, b.x, b.y);
        }
        sY[r0*64 + col]       = sXr[r0*64 + col]       + d.x;
        sY[r0*64 + col+1]     = sXr[r0*64 + col+1]     + d.y;
        sY[(r0+8)*64 + col]   = sXr[(r0+8)*64 + col]   + d.z;
        sY[(r0+8)*64 + col+1] = sXr[(r0+8)*64 + col+1] + d.w;
    }
    __syncthreads();

    // LN
    {
        int r = t >> 4, l = t & 15;
        float4 v = *(const float4*)&sY[r*64 + l*4];
        float s  = v.x + v.y + v.z + v.w;
        float ss = v.x*v.x + v.y*v.y + v.z*v.z + v.w*v.w;
        #pragma unroll
        for (int o = 1; o < 16; o <<= 1) {
            s  += __shfl_xor_sync(0xffffffffu, s,  o, 16);
            ss += __shfl_xor_sync(0xffffffffu, ss, o, 16);
        }
        if (l == 0) {
            float m = s * (1.f/64.f);
            float var = ss * (1.f/64.f) - m*m;
            smean[r] = m; sinv[r] = rsqrtf(var + 1e-5f);
        }
    }
    __syncthreads();
    for (int i = t; i < 2048; i += 512) {
        int r = i >> 6, cc = i & 63;
        g_x2[(rbase + r)*64 + cc] = (sY[i] - smean[r]) * sinv[r] * ssg[cc] + ssb[cc];
    }
}

// ---------------- K6: FFN via tf32 MMA + residual + LN -> d_out --------------
__global__ __launch_bounds__(512) void ffn_kernel(
    const float* __restrict__ fb1, const float* __restrict__ fb2,
    const float* __restrict__ fg,  const float* __restrict__ fb,
    float* __restrict__ out)
{
    extern __shared__ float sm[];
    float* sA   = sm;               // X 32 x 68 tf32
    float* sH   = sA + 2176;        // H 32 x 260 tf32
    float* sXr  = sH + 8320;        // 32 x 64 fp32
    float* sY   = sXr + 2048;       // 32 x 64
    float* sb1  = sY + 2048;        // 256
    float* sb2  = sb1 + 256;        // 64
    float* sfg  = sb2 + 64;
    float* sfb  = sfg + 64;
    float* smean= sfb + 64;         // 32
    float* sinv = smean + 32;       // 32

    int t = threadIdx.x;
    if (t < 256) sb1[t] = fb1[t];
    if (t < 64) { sb2[t] = fb2[t]; sfg[t] = fg[t]; sfb[t] = fb[t]; }

    int rbase = blockIdx.x * 32;
    for (int idx = t; idx < 2048; idx += 512) {
        int c = idx & 63, r = idx >> 6;
        float v = g_x2[(rbase + r)*64 + c];
        sXr[r*64 + c] = v;
        sA[r*68 + c] = to_tf32(v);
    }
    __syncthreads();

    int w = t >> 5, lane = t & 31, g = lane >> 2, tg = lane & 3;

    // Stage1: H = gelu(X @ W1 + b1)
    {
        int mt = w >> 3, ng = w & 7;
        float4 d[4];
        #pragma unroll
        for (int i = 0; i < 4; i++) {
            int col = (ng*4 + i)*8 + 2*tg;
            d[i] = make_float4(sb1[col], sb1[col+1], sb1[col], sb1[col+1]);
        }
        #pragma unroll
        for (int kt = 0; kt < 8; kt++) {
            const float* Ab = sA + (mt*16)*68 + kt*8;
            float a0 = Ab[g*68 + tg],     a1 = Ab[(g+8)*68 + tg];
            float a2 = Ab[g*68 + tg + 4], a3 = Ab[(g+8)*68 + tg + 4];
            #pragma unroll
            for (int i = 0; i < 4; i++) {
                int nt = ng*4 + i;
                float2 b = __ldg((const float2*)&g_F1f[((((kt<<5) + nt)<<5) + lane)*2]);
                mma_tf32(d[i], a0, a1, a2, a3, b.x, b.y);
            }
        }
        int r0 = mt*16 + g;
        #pragma unroll
        for (int i = 0; i < 4; i++) {
            int col = (ng*4 + i)*8 + 2*tg;
            *(float2*)&sH[r0*260 + col]     = make_float2(to_tf32(gelu_f(d[i].x)), to_tf32(gelu_f(d[i].y)));
            *(float2*)&sH[(r0+8)*260 + col] = make_float2(to_tf32(gelu_f(d[i].z)), to_tf32(gelu_f(d[i].w)));
        }
    }
    __syncthreads();

    // Stage2: Y = X + H @ W2 + b2
    {
        int mt = w >> 3, nt = w & 7;
        int col = nt*8 + 2*tg;
        int r0 = mt*16 + g;
        float4 d = make_float4(sb2[col], sb2[col+1], sb2[col], sb2[col+1]);
        #pragma unroll
        for (int kt = 0; kt < 32; kt++) {
            const float* Ab = sH + (mt*16)*260 + kt*8;
            float a0 = Ab[g*260 + tg],     a1 = Ab[(g+8)*260 + tg];
            float a2 = Ab[g*260 + tg + 4], a3 = Ab[(g+8)*260 + tg + 4];
            float2 b = __ldg((const float2*)&g_F2f[((((kt<<3) + nt)<<5) + lane)*2]);
            mma_tf32(d, a0, a1, a2, a3, b.x, b.y);
        }
        sY[r0*64 + col]       = sXr[r0*64 + col]       + d.x;
        sY[r0*64 + col+1]     = sXr[r0*64 + col+1]     + d.y;
        sY[(r0+8)*64 + col]   = sXr[(r0+8)*64 + col]   + d.z;
        sY[(r0+8)*64 + col+1] = sXr[(r0+8)*64 + col+1] + d.w;
    }
    __syncthreads();

    // LN
    {
        int r = t >> 4, l = t & 15;
        float4 v = *(const float4*)&sY[r*64 + l*4];
        float s  = v.x + v.y + v.z + v.w;
        float ss = v.x*v.x + v.y*v.y + v.z*v.z + v.w*v.w;
        #pragma unroll
        for (int o = 1; o < 16; o <<= 1) {
            s  += __shfl_xor_sync(0xffffffffu, s,  o, 16);
            ss += __shfl_xor_sync(0xffffffffu, ss, o, 16);
        }
        if (l == 0) {
            float m = s * (1.f/64.f);
            float var = ss * (1.f/64.f) - m*m;
            smean[r] = m; sinv[r] = rsqrtf(var + 1e-5f);
        }
    }
    __syncthreads();
    for (int i = t; i < 2048; i += 512) {
        int r = i >> 6, cc = i & 63;
        out[(rbase + r)*64 + cc] = (sY[i] - smean[r]) * sinv[r] * sfg[cc] + sfb[cc];
    }
}

// ---------------- host launcher ---------------------------------------------
extern "C" void kernel_launch(void* const* d_in, const int* in_sizes, int n_in,
                              void* d_out, int out_size)
{
    (void)in_sizes; (void)n_in; (void)out_size;
    const float* x    = (const float*)d_in[0];
    const int*   ei   = (const int*)  d_in[1];
    const float* ea   = (const float*)d_in[2];
    const float* ipw  = (const float*)d_in[3];
    const float* ipb  = (const float*)d_in[4];
    const float* opw  = (const float*)d_in[5];
    const float* opb  = (const float*)d_in[6];
    const float* tng  = (const float*)d_in[7];
    const float* tnb  = (const float*)d_in[8];
    const float* ew1  = (const float*)d_in[9];
    const float* eb1  = (const float*)d_in[10];
    const float* ew2  = (const float*)d_in[11];
    const float* eb2  = (const float*)d_in[12];
    const float* mw1  = (const float*)d_in[13];
    const float* mb1  = (const float*)d_in[14];
    const float* mw2  = (const float*)d_in[15];
    const float* mb2  = (const float*)d_in[16];
    const float* uw1  = (const float*)d_in[17];
    const float* ub1  = (const float*)d_in[18];
    const float* uw2  = (const float*)d_in[19];
    const float* ub2  = (const float*)d_in[20];
    const float* sng  = (const float*)d_in[21];
    const float* snb  = (const float*)d_in[22];
    const float* fw1  = (const float*)d_in[23];
    const float* fb1  = (const float*)d_in[24];
    const float* fw2  = (const float*)d_in[25];
    const float* fb2  = (const float*)d_in[26];
    const float* fng  = (const float*)d_in[27];
    const float* fnb  = (const float*)d_in[28];
    float* out = (float*)d_out;

    const int SM_ATT = 25344 * 4;   // 101376
    const int SM_EE  = 12736 * 4;
    const int SM_PQ  = 2176 * 4;    // 8704
    const int SM_UPD = 15136 * 4;   // 60544
    const int SM_FFN = 15104 * 4;   // 60416
    cudaFuncSetAttribute(attn_kernel,     cudaFuncAttributeMaxDynamicSharedMemorySize, SM_ATT);
    cudaFuncSetAttribute(edge_emb_kernel, cudaFuncAttributeMaxDynamicSharedMemorySize, SM_EE);
    cudaFuncSetAttribute(pq_kernel,       cudaFuncAttributeMaxDynamicSharedMemorySize, SM_PQ);
    cudaFuncSetAttribute(update_kernel,   cudaFuncAttributeMaxDynamicSharedMemorySize, SM_UPD);
    cudaFuncSetAttribute(ffn_kernel,      cudaFuncAttributeMaxDynamicSharedMemorySize, SM_FFN);

    // launch order: position 4 gets captured by ncu -> attn this time
    prep_kernel      <<<168, 512>>>(ipw, opw, mw1, mw2, uw1, uw2, fw1, fw2);
    csr_zero_kernel  <<<20, 256>>>();
    csr_count_kernel <<<79, 256>>>(ei);
    attn_kernel      <<<2500, 512, SM_ATT>>>(x, ipb, opb, tng, tnb);
    csr_scan_kernel  <<<1, 1024>>>();
    csr_fill_kernel  <<<79, 256>>>(ei);
    edge_emb_kernel  <<<256, 128, SM_EE>>>(ea, ew1, eb1, ew2, eb2, mw1, mb1);
    pq_kernel        <<<5000, 512, SM_PQ>>>();
    aggr_kernel      <<<20000, 256>>>();
    update_kernel    <<<5000, 512, SM_UPD>>>(mb2, ub1, ub2, sng, snb);
    ffn_kernel       <<<5000, 512, SM_FFN>>>(fb1, fb2, fng, fnb, out);
}